// round 1
// baseline (speedup 1.0000x reference)
#include <cuda_runtime.h>
#include <math.h>

// ---------------- problem constants (hardcoded) ----------------
constexpr int   Bb   = 4;
constexpr int   Ss   = 2048;
constexpr int   DIN  = 256;
constexpr int   Dd   = 512;
constexpr int   Hh   = 8;
constexpr int   DOUT = 128;
constexpr int   HD   = 64;       // Dd / Hh
constexpr int   BS   = Bb * Ss;  // 8192 rows
constexpr float SCALE = 0.125f;  // 1/sqrt(64)

// ---------------- scratch (static device memory; no allocs) ----------------
constexpr size_t NBD  = (size_t)BS * Dd;        // 4,194,304 floats
constexpr size_t O_H   = 0;
constexpr size_t O_Q   = 1 * NBD;
constexpr size_t O_K   = 2 * NBD;
constexpr size_t O_V   = 3 * NBD;
constexpr size_t O_AO  = 4 * NBD;
constexpr size_t O_LOC = 5 * NBD;
constexpr size_t O_GLO = 6 * NBD;
constexpr size_t O_FUS = 7 * NBD;
constexpr size_t O_H1  = 8 * NBD;
constexpr size_t O_FFN = 9 * NBD;
constexpr size_t O_H3  = 10 * NBD;
constexpr size_t O_T1  = 11 * NBD;              // 2*NBD wide (FFN hidden)
constexpr size_t O_PP  = 13 * NBD;              // 16 * B * D partials
constexpr size_t O_P   = 13 * NBD + (size_t)16 * Bb * Dd;
constexpr size_t SCRATCH_FLOATS = O_P + (size_t)Bb * Dd;

__device__ float g_scratch[SCRATCH_FLOATS];

// ---------------- generic tiled GEMM, fused epilogues ----------------
// C[M,N] = A[M,K] @ W[K,N] (+epilogue). A row-major lda, W row-major N.
// MODE 0: +bias
// MODE 1: +bias + pos[(row%S)*N + col]
// MODE 2: relu(+bias)
// MODE 3: A is concat(A, A2) along K (each stride lda, split at KA);
//         g = tanh(relu(acc+bias)); C = g*p1 + (1-g)*p2   (the gate+blend)
template <int MODE>
__global__ void __launch_bounds__(256) gemm_k(
    const float* __restrict__ A, const float* __restrict__ A2, int lda, int KA,
    const float* __restrict__ W, const float* __restrict__ bias,
    const float* __restrict__ p1, const float* __restrict__ p2,
    float* __restrict__ C, int M, int N, int K)
{
    __shared__ float As[16][64];
    __shared__ float Bs[16][64];

    const int t  = threadIdx.x;
    const int tx = t & 15, ty = t >> 4;
    const int n0 = blockIdx.x * 64, m0 = blockIdx.y * 64;

    const int ar = t >> 2, ac = (t & 3) * 4;   // A-tile loader: 64 rows x 16 cols
    const int br = t >> 4, bc = (t & 15) * 4;  // W-tile loader: 16 rows x 64 cols

    float acc[4][4] = {};

    for (int k0 = 0; k0 < K; k0 += 16) {
        const float* Asrc = A;
        int kk0 = k0;
        if (MODE == 3 && k0 >= KA) { Asrc = A2; kk0 = k0 - KA; }

        float4 av = *(const float4*)(Asrc + (size_t)(m0 + ar) * lda + kk0 + ac);
        As[ac + 0][ar] = av.x;
        As[ac + 1][ar] = av.y;
        As[ac + 2][ar] = av.z;
        As[ac + 3][ar] = av.w;
        *(float4*)&Bs[br][bc] = *(const float4*)(W + (size_t)(k0 + br) * N + n0 + bc);
        __syncthreads();

#pragma unroll
        for (int kk = 0; kk < 16; kk++) {
            float4 a = *(const float4*)&As[kk][ty * 4];
            float4 b = *(const float4*)&Bs[kk][tx * 4];
            float aa[4] = {a.x, a.y, a.z, a.w};
            float bb[4] = {b.x, b.y, b.z, b.w};
#pragma unroll
            for (int i = 0; i < 4; i++)
#pragma unroll
                for (int j = 0; j < 4; j++) acc[i][j] += aa[i] * bb[j];
        }
        __syncthreads();
    }

#pragma unroll
    for (int i = 0; i < 4; i++) {
        const int row = m0 + ty * 4 + i;
#pragma unroll
        for (int j = 0; j < 4; j++) {
            const int col = n0 + tx * 4 + j;
            float v = acc[i][j] + bias[col];
            if (MODE == 1) v += p1[(size_t)(row & (Ss - 1)) * N + col];
            if (MODE == 2) v = fmaxf(v, 0.f);
            if (MODE == 3) {
                float g = tanhf(fmaxf(v, 0.f));
                v = g * p1[(size_t)row * N + col] + (1.f - g) * p2[(size_t)row * N + col];
            }
            C[(size_t)row * N + col] = v;
        }
    }
}

// ---------------- global attention: fp32 flash, 64-query tiles ----------------
// Q/K/V layout: [(b*S+s)*D + h*HD + d]. grid = (S/64, H, B), block = 128.
// Thread t owns query qi = t/2, dims [half*32, half*32+32).
__global__ void __launch_bounds__(128) flash_attn_k(
    const float* __restrict__ Q, const float* __restrict__ K,
    const float* __restrict__ V, float* __restrict__ O)
{
    const int qt = blockIdx.x, h = blockIdx.y, b = blockIdx.z;
    const int t = threadIdx.x;
    const int qi = t >> 1, half = t & 1;
    const int q = qt * 64 + qi;

    __shared__ float Ks[64][64];
    __shared__ float Vs[64][64];
    __shared__ float Sc[64][64];   // Sc[key][query] (transposed: conflict-free writes)

    const float* qrow = Q + ((size_t)(b * Ss + q)) * Dd + h * HD + half * 32;
    float qreg[32], acc[32];
#pragma unroll
    for (int i = 0; i < 32; i++) { qreg[i] = qrow[i] * SCALE; acc[i] = 0.f; }

    float m = -INFINITY, l = 0.f;

    for (int k0 = 0; k0 < Ss; k0 += 64) {
        for (int idx = t; idx < 1024; idx += 128) {
            int r = idx >> 4, c = (idx & 15) * 4;
            size_t base = ((size_t)(b * Ss + k0 + r)) * Dd + h * HD + c;
            *(float4*)&Ks[r][c] = *(const float4*)(K + base);
            *(float4*)&Vs[r][c] = *(const float4*)(V + base);
        }
        __syncthreads();

        float mt = -INFINITY;
#pragma unroll 4
        for (int j = 0; j < 64; j++) {
            float s = 0.f;
#pragma unroll
            for (int i = 0; i < 32; i += 4) {
                float4 kv = *(const float4*)&Ks[j][half * 32 + i];
                s += qreg[i] * kv.x + qreg[i + 1] * kv.y + qreg[i + 2] * kv.z + qreg[i + 3] * kv.w;
            }
            s += __shfl_xor_sync(0xffffffffu, s, 1);   // combine two halves
            if (!half) Sc[j][qi] = s;
            mt = fmaxf(mt, s);
        }
        __syncwarp();

        const float mn = fmaxf(m, mt);
        const float alpha = __expf(m - mn);
        l *= alpha;
#pragma unroll
        for (int i = 0; i < 32; i++) acc[i] *= alpha;
        m = mn;

#pragma unroll 4
        for (int j = 0; j < 64; j++) {
            float p = __expf(Sc[j][qi] - mn);
            l += p;
#pragma unroll
            for (int i = 0; i < 32; i += 4) {
                float4 vv = *(const float4*)&Vs[j][half * 32 + i];
                acc[i]     += p * vv.x;
                acc[i + 1] += p * vv.y;
                acc[i + 2] += p * vv.z;
                acc[i + 3] += p * vv.w;
            }
        }
        __syncthreads();
    }

    const float inv = 1.f / l;
    float* orow = O + ((size_t)(b * Ss + q)) * Dd + h * HD + half * 32;
#pragma unroll
    for (int i = 0; i < 32; i++) orow[i] = acc[i] * inv;
}

// ---------------- local banded attention: warp per (b,h,q) ----------------
// band: keys in [q-W/2, q+W/2] -> identical to -inf mask + full softmax.
__global__ void __launch_bounds__(128) local_attn_k(
    const float* __restrict__ Q, const float* __restrict__ K,
    const float* __restrict__ V, float* __restrict__ O)
{
    const int wid = threadIdx.x >> 5, lane = threadIdx.x & 31;
    const int gw = blockIdx.x * 4 + wid;        // ((b*H + h)*S + q)
    const int q = gw & (Ss - 1);
    const int bh = gw / Ss;
    const int h = bh & (Hh - 1);
    const int b = bh / Hh;

    __shared__ float sc[4][80];

    const float* qp = Q + ((size_t)(b * Ss + q)) * Dd + h * HD;
    const float q0 = qp[lane] * SCALE;
    const float q1 = qp[lane + 32] * SCALE;

    const int jlo = max(0, q - 32), jhi = min(Ss - 1, q + 32);
    const int n = jhi - jlo + 1;

    float m = -INFINITY;
    for (int j = jlo; j <= jhi; j++) {
        const float* kp = K + ((size_t)(b * Ss + j)) * Dd + h * HD;
        float s = q0 * kp[lane] + q1 * kp[lane + 32];
#pragma unroll
        for (int o = 16; o; o >>= 1) s += __shfl_xor_sync(0xffffffffu, s, o);
        if (!lane) sc[wid][j - jlo] = s;
        m = fmaxf(m, s);
    }
    __syncwarp();

    float l = 0.f;
    for (int idx = lane; idx < n; idx += 32) {
        float p = __expf(sc[wid][idx] - m);
        sc[wid][idx] = p;
        l += p;
    }
#pragma unroll
    for (int o = 16; o; o >>= 1) l += __shfl_xor_sync(0xffffffffu, l, o);
    __syncwarp();

    float a0 = 0.f, a1 = 0.f;
    for (int j = jlo; j <= jhi; j++) {
        const float p = sc[wid][j - jlo];
        const float* vp = V + ((size_t)(b * Ss + j)) * Dd + h * HD;
        a0 += p * vp[lane];
        a1 += p * vp[lane + 32];
    }
    const float inv = 1.f / l;
    float* op = O + ((size_t)(b * Ss + q)) * Dd + h * HD;
    op[lane] = a0 * inv;
    op[lane + 32] = a1 * inv;
}

// ---------------- LayerNorm kernels (row = 512, block = 128) ----------------
__global__ void __launch_bounds__(128) ln_add_k(
    const float* __restrict__ A, const float* __restrict__ R,
    const float* __restrict__ g, const float* __restrict__ be,
    float* __restrict__ O)
{
    const int row = blockIdx.x, t = threadIdx.x;
    const size_t base = (size_t)row * Dd + t * 4;
    float4 a = *(const float4*)(A + base);
    float4 r = *(const float4*)(R + base);
    float x[4] = {a.x + r.x, a.y + r.y, a.z + r.z, a.w + r.w};

    float s = x[0] + x[1] + x[2] + x[3];
    float ss = x[0]*x[0] + x[1]*x[1] + x[2]*x[2] + x[3]*x[3];
    __shared__ float sh1[4], sh2[4];
#pragma unroll
    for (int o = 16; o; o >>= 1) {
        s  += __shfl_xor_sync(0xffffffffu, s, o);
        ss += __shfl_xor_sync(0xffffffffu, ss, o);
    }
    if (!(t & 31)) { sh1[t >> 5] = s; sh2[t >> 5] = ss; }
    __syncthreads();
    s  = sh1[0] + sh1[1] + sh1[2] + sh1[3];
    ss = sh2[0] + sh2[1] + sh2[2] + sh2[3];

    const float mean = s * (1.f / Dd);
    const float var = ss * (1.f / Dd) - mean * mean;
    const float rs = rsqrtf(var + 1e-5f);
    float4 gg = *(const float4*)(g + t * 4);
    float4 bb = *(const float4*)(be + t * 4);
    float4 o4;
    o4.x = (x[0] - mean) * rs * gg.x + bb.x;
    o4.y = (x[1] - mean) * rs * gg.y + bb.y;
    o4.z = (x[2] - mean) * rs * gg.z + bb.z;
    o4.w = (x[3] - mean) * rs * gg.w + bb.w;
    *(float4*)(O + base) = o4;
}

// h3 = LN( LN(A+R, g2,b2), g3,b3 )  — two LNs fused
__global__ void __launch_bounds__(128) ln_add_ln_k(
    const float* __restrict__ A, const float* __restrict__ R,
    const float* __restrict__ g2, const float* __restrict__ b2,
    const float* __restrict__ g3, const float* __restrict__ b3,
    float* __restrict__ O)
{
    const int row = blockIdx.x, t = threadIdx.x;
    const size_t base = (size_t)row * Dd + t * 4;
    float4 a = *(const float4*)(A + base);
    float4 r = *(const float4*)(R + base);
    float x[4] = {a.x + r.x, a.y + r.y, a.z + r.z, a.w + r.w};

    __shared__ float sh1[4], sh2[4];
    float s = x[0] + x[1] + x[2] + x[3];
    float ss = x[0]*x[0] + x[1]*x[1] + x[2]*x[2] + x[3]*x[3];
#pragma unroll
    for (int o = 16; o; o >>= 1) {
        s  += __shfl_xor_sync(0xffffffffu, s, o);
        ss += __shfl_xor_sync(0xffffffffu, ss, o);
    }
    if (!(t & 31)) { sh1[t >> 5] = s; sh2[t >> 5] = ss; }
    __syncthreads();
    s  = sh1[0] + sh1[1] + sh1[2] + sh1[3];
    ss = sh2[0] + sh2[1] + sh2[2] + sh2[3];
    float mean = s * (1.f / Dd);
    float var = ss * (1.f / Dd) - mean * mean;
    float rs = rsqrtf(var + 1e-5f);

    float4 gg = *(const float4*)(g2 + t * 4);
    float4 bb = *(const float4*)(b2 + t * 4);
    float y[4];
    y[0] = (x[0] - mean) * rs * gg.x + bb.x;
    y[1] = (x[1] - mean) * rs * gg.y + bb.y;
    y[2] = (x[2] - mean) * rs * gg.z + bb.z;
    y[3] = (x[3] - mean) * rs * gg.w + bb.w;

    __syncthreads();  // reuse sh1/sh2
    s  = y[0] + y[1] + y[2] + y[3];
    ss = y[0]*y[0] + y[1]*y[1] + y[2]*y[2] + y[3]*y[3];
#pragma unroll
    for (int o = 16; o; o >>= 1) {
        s  += __shfl_xor_sync(0xffffffffu, s, o);
        ss += __shfl_xor_sync(0xffffffffu, ss, o);
    }
    if (!(t & 31)) { sh1[t >> 5] = s; sh2[t >> 5] = ss; }
    __syncthreads();
    s  = sh1[0] + sh1[1] + sh1[2] + sh1[3];
    ss = sh2[0] + sh2[1] + sh2[2] + sh2[3];
    mean = s * (1.f / Dd);
    var = ss * (1.f / Dd) - mean * mean;
    rs = rsqrtf(var + 1e-5f);

    float4 g3v = *(const float4*)(g3 + t * 4);
    float4 b3v = *(const float4*)(b3 + t * 4);
    float4 o4;
    o4.x = (y[0] - mean) * rs * g3v.x + b3v.x;
    o4.y = (y[1] - mean) * rs * g3v.y + b3v.y;
    o4.z = (y[2] - mean) * rs * g3v.z + b3v.z;
    o4.w = (y[3] - mean) * rs * g3v.w + b3v.w;
    *(float4*)(O + base) = o4;
}

// ---------------- mean pool over S (deterministic 2-stage) ----------------
__global__ void __launch_bounds__(128) colmean_part_k(const float* __restrict__ X,
                                                      float* __restrict__ PP)
{
    const int b = blockIdx.x >> 2;
    const int d = (blockIdx.x & 3) * 128 + threadIdx.x;
    const int sc = blockIdx.y;  // 16 chunks of 128
    float s = 0.f;
    for (int j = sc * 128; j < sc * 128 + 128; j++)
        s += X[((size_t)(b * Ss + j)) * Dd + d];
    PP[((size_t)sc * Bb + b) * Dd + d] = s;
}

__global__ void __launch_bounds__(128) colmean_fin_k(const float* __restrict__ PP,
                                                     float* __restrict__ P)
{
    const int idx = blockIdx.x * 128 + threadIdx.x;  // 0..B*D-1
    const int b = idx / Dd, d = idx % Dd;
    float s = 0.f;
#pragma unroll
    for (int c = 0; c < 16; c++) s += PP[((size_t)c * Bb + b) * Dd + d];
    P[idx] = s * (1.f / Ss);
}

// ---------------- final tiny GEMM: out[b,o] = pooled[b,:] @ out_w + out_b ----
__global__ void __launch_bounds__(128) final_k(const float* __restrict__ P,
                                               const float* __restrict__ Wt,
                                               const float* __restrict__ bias,
                                               float* __restrict__ out)
{
    const int b = blockIdx.x, o = threadIdx.x;
    float s = bias[o];
    for (int d = 0; d < Dd; d++) s += P[b * Dd + d] * Wt[d * DOUT + o];
    out[b * DOUT + o] = s;
}

// ---------------- launch ----------------
extern "C" void kernel_launch(void* const* d_in, const int* in_sizes, int n_in,
                              void* d_out, int out_size)
{
    const float* x      = (const float*)d_in[0];
    const float* pos    = (const float*)d_in[1];
    const float* win_w  = (const float*)d_in[2];
    const float* win_b  = (const float*)d_in[3];
    const float* l_wqkv = (const float*)d_in[4];
    const float* l_bqkv = (const float*)d_in[5];
    const float* l_wo   = (const float*)d_in[6];
    const float* l_bo   = (const float*)d_in[7];
    const float* g_wqkv = (const float*)d_in[8];
    const float* g_bqkv = (const float*)d_in[9];
    const float* g_wo   = (const float*)d_in[10];
    const float* g_bo   = (const float*)d_in[11];
    const float* gate_w = (const float*)d_in[12];
    const float* gate_b = (const float*)d_in[13];
    const float* ffn_w1 = (const float*)d_in[14];
    const float* ffn_b1 = (const float*)d_in[15];
    const float* ffn_w2 = (const float*)d_in[16];
    const float* ffn_b2 = (const float*)d_in[17];
    const float* n1_g   = (const float*)d_in[18];
    const float* n1_b   = (const float*)d_in[19];
    const float* n2_g   = (const float*)d_in[20];
    const float* n2_b   = (const float*)d_in[21];
    const float* n3_g   = (const float*)d_in[22];
    const float* n3_b   = (const float*)d_in[23];
    const float* out_w  = (const float*)d_in[24];
    const float* out_b  = (const float*)d_in[25];

    float* sp = nullptr;
    cudaGetSymbolAddress((void**)&sp, g_scratch);
    float* bH   = sp + O_H;
    float* bQ   = sp + O_Q;
    float* bK   = sp + O_K;
    float* bV   = sp + O_V;
    float* bAO  = sp + O_AO;
    float* bLOC = sp + O_LOC;
    float* bGLO = sp + O_GLO;
    float* bFUS = sp + O_FUS;
    float* bH1  = sp + O_H1;
    float* bFFN = sp + O_FFN;
    float* bH3  = sp + O_H3;
    float* bT1  = sp + O_T1;
    float* bPP  = sp + O_PP;
    float* bP   = sp + O_P;

    const dim3 blk(256);
    const dim3 gD(Dd / 64, BS / 64);        // N=512 GEMMs
    const dim3 gD2(2 * Dd / 64, BS / 64);   // N=1024 GEMM

    // 1. h = x @ win_w + win_b + pos
    gemm_k<1><<<gD, blk>>>(x, nullptr, DIN, 0, win_w, win_b, pos, nullptr,
                           bH, BS, Dd, DIN);

    // 2. local QKV
    float* qkv[3] = {bQ, bK, bV};
    for (int i = 0; i < 3; i++)
        gemm_k<0><<<gD, blk>>>(bH, nullptr, Dd, 0, l_wqkv + (size_t)i * Dd * Dd,
                               l_bqkv + i * Dd, nullptr, nullptr, qkv[i], BS, Dd, Dd);

    // 3. local banded attention
    local_attn_k<<<(Bb * Hh * Ss) / 4, 128>>>(bQ, bK, bV, bAO);

    // 4. local_out = attn_o @ l_wo + l_bo
    gemm_k<0><<<gD, blk>>>(bAO, nullptr, Dd, 0, l_wo, l_bo, nullptr, nullptr,
                           bLOC, BS, Dd, Dd);

    // 5. global QKV
    for (int i = 0; i < 3; i++)
        gemm_k<0><<<gD, blk>>>(bH, nullptr, Dd, 0, g_wqkv + (size_t)i * Dd * Dd,
                               g_bqkv + i * Dd, nullptr, nullptr, qkv[i], BS, Dd, Dd);

    // 6. global flash attention
    flash_attn_k<<<dim3(Ss / 64, Hh, Bb), 128>>>(bQ, bK, bV, bAO);

    // 7. global_out
    gemm_k<0><<<gD, blk>>>(bAO, nullptr, Dd, 0, g_wo, g_bo, nullptr, nullptr,
                           bGLO, BS, Dd, Dd);

    // 8. gate GEMM fused with blend: fused = g*local + (1-g)*global
    gemm_k<3><<<gD, blk>>>(bLOC, bGLO, Dd, Dd, gate_w, gate_b, bLOC, bGLO,
                           bFUS, BS, Dd, 2 * Dd);

    // 9. h1 = LN(h + fused)
    ln_add_k<<<BS, 128>>>(bH, bFUS, n1_g, n1_b, bH1);

    // 10. FFN
    gemm_k<2><<<gD2, blk>>>(bH1, nullptr, Dd, 0, ffn_w1, ffn_b1, nullptr, nullptr,
                            bT1, BS, 2 * Dd, Dd);
    gemm_k<0><<<gD, blk>>>(bT1, nullptr, 2 * Dd, 0, ffn_w2, ffn_b2, nullptr, nullptr,
                           bFFN, BS, Dd, 2 * Dd);

    // 11. h3 = LN(LN(h1 + ffn))
    ln_add_ln_k<<<BS, 128>>>(bH1, bFFN, n2_g, n2_b, n3_g, n3_b, bH3);

    // 12. mean-pool over S, then final projection
    colmean_part_k<<<dim3(Bb * 4, 16), 128>>>(bH3, bPP);
    colmean_fin_k<<<(Bb * Dd) / 128, 128>>>(bPP, bP);
    final_k<<<Bb, DOUT>>>(bP, out_w, out_b, (float*)d_out);

    (void)in_sizes; (void)n_in; (void)out_size;
}

// round 2
// speedup vs baseline: 1.4413x; 1.4413x over previous
#include <cuda_runtime.h>
#include <math.h>

// ---------------- problem constants (hardcoded) ----------------
constexpr int   Bb   = 4;
constexpr int   Ss   = 2048;
constexpr int   DIN  = 256;
constexpr int   Dd   = 512;
constexpr int   Hh   = 8;
constexpr int   DOUT = 128;
constexpr int   HD   = 64;       // Dd / Hh
constexpr int   BS   = Bb * Ss;  // 8192 rows
constexpr float SCALE = 0.125f;  // 1/sqrt(64)

// ---------------- scratch (static device memory; no allocs) ----------------
constexpr size_t NBD  = (size_t)BS * Dd;        // 4,194,304 floats
constexpr size_t O_H   = 0;
constexpr size_t O_Q   = 1 * NBD;
constexpr size_t O_K   = 2 * NBD;
constexpr size_t O_V   = 3 * NBD;
constexpr size_t O_AO  = 4 * NBD;
constexpr size_t O_LOC = 5 * NBD;
constexpr size_t O_GLO = 6 * NBD;
constexpr size_t O_FUS = 7 * NBD;
constexpr size_t O_H1  = 8 * NBD;
constexpr size_t O_FFN = 9 * NBD;
constexpr size_t O_H3  = 10 * NBD;
constexpr size_t O_T1  = 11 * NBD;              // 2*NBD wide (FFN hidden)
constexpr size_t O_PP  = 13 * NBD;              // 16 * B * D partials
constexpr size_t O_P   = 13 * NBD + (size_t)16 * Bb * Dd;
constexpr size_t SCRATCH_FLOATS = O_P + (size_t)Bb * Dd;

__device__ float g_scratch[SCRATCH_FLOATS];

// ---------------- 128x128 tiled GEMM, 8x8 microtile, fused epilogues ------
// C[M,N] = A[M,K] @ W[K,N] (+epilogue). A row-major lda, W row-major N.
// MODE 0: +bias
// MODE 1: +bias + pos[(row%S)*N + col]
// MODE 2: relu(+bias)
// MODE 3: A is concat(A, A2) along K (split at KA);
//         g = tanh(relu(acc+bias)); C = g*p1 + (1-g)*p2
template <int MODE>
__global__ void __launch_bounds__(256) gemm128_k(
    const float* __restrict__ A, const float* __restrict__ A2, int lda, int KA,
    const float* __restrict__ W, const float* __restrict__ bias,
    const float* __restrict__ p1, const float* __restrict__ p2,
    float* __restrict__ C, int M, int N, int K)
{
    __shared__ float As[16][128];   // [k][m]
    __shared__ float Bs[16][128];   // [k][n]

    const int t  = threadIdx.x;
    const int tx = t & 15, ty = t >> 4;
    const int n0 = blockIdx.x * 128, m0 = blockIdx.y * 128;

    const int amr = t >> 1;            // A loader: row 0..127
    const int akc = (t & 1) * 8;       // A loader: col 0 or 8
    const int bkr = t >> 4;            // B loader: k-row 0..15
    const int bnc = (t & 15) * 8;      // B loader: col 0..120

    float acc[8][8] = {};

    for (int k0 = 0; k0 < K; k0 += 16) {
        const float* Asrc = A;
        int kk0 = k0;
        if (MODE == 3 && k0 >= KA) { Asrc = A2; kk0 = k0 - KA; }

        float4 a0 = *(const float4*)(Asrc + (size_t)(m0 + amr) * lda + kk0 + akc);
        float4 a1 = *(const float4*)(Asrc + (size_t)(m0 + amr) * lda + kk0 + akc + 4);
        As[akc + 0][amr] = a0.x; As[akc + 1][amr] = a0.y;
        As[akc + 2][amr] = a0.z; As[akc + 3][amr] = a0.w;
        As[akc + 4][amr] = a1.x; As[akc + 5][amr] = a1.y;
        As[akc + 6][amr] = a1.z; As[akc + 7][amr] = a1.w;
        *(float4*)&Bs[bkr][bnc]     = *(const float4*)(W + (size_t)(k0 + bkr) * N + n0 + bnc);
        *(float4*)&Bs[bkr][bnc + 4] = *(const float4*)(W + (size_t)(k0 + bkr) * N + n0 + bnc + 4);
        __syncthreads();

#pragma unroll
        for (int kk = 0; kk < 16; kk++) {
            float a[8], b[8];
            *(float4*)(a)     = *(const float4*)&As[kk][ty * 8];
            *(float4*)(a + 4) = *(const float4*)&As[kk][ty * 8 + 4];
            *(float4*)(b)     = *(const float4*)&Bs[kk][tx * 8];
            *(float4*)(b + 4) = *(const float4*)&Bs[kk][tx * 8 + 4];
#pragma unroll
            for (int i = 0; i < 8; i++)
#pragma unroll
                for (int j = 0; j < 8; j++) acc[i][j] += a[i] * b[j];
        }
        __syncthreads();
    }

#pragma unroll
    for (int i = 0; i < 8; i++) {
        const int row = m0 + ty * 8 + i;
        float o[8];
#pragma unroll
        for (int j = 0; j < 8; j++) {
            const int col = n0 + tx * 8 + j;
            float v = acc[i][j] + bias[col];
            if (MODE == 1) v += p1[(size_t)(row & (Ss - 1)) * N + col];
            if (MODE == 2) v = fmaxf(v, 0.f);
            if (MODE == 3) {
                float g = tanhf(fmaxf(v, 0.f));
                v = g * p1[(size_t)row * N + col] + (1.f - g) * p2[(size_t)row * N + col];
            }
            o[j] = v;
        }
        *(float4*)(C + (size_t)row * N + n0 + tx * 8)     = *(float4*)(o);
        *(float4*)(C + (size_t)row * N + n0 + tx * 8 + 4) = *(float4*)(o + 4);
    }
}

// ---------------- global attention: GEMM-structured fp32 flash -------------
// Q-tile 128, K-tile 64, 256 threads. Thread (tx=t&15, ty=t>>4) owns
// q rows qt*128 + ty*8 .. +8 for BOTH the score microtile (8q x 4k) and the
// output accumulator (8q x 4d), so softmax row state stays in registers and
// reduces across the 16-lane tx group via shfl_xor.
// dynamic smem layout (floats):
//   Qts [64][128] : Q transposed (d-major), pre-scaled        @ 0
//   Ps  [64][132] : P transposed (k-major), padded            @ 8192
//   Ks  [64][68]  : K transposed (d-major), padded            @ 16640
//   Vs  [64][68]  : V row-major (k-major), padded             @ 20992
constexpr int FL_QTS = 0;
constexpr int FL_PS  = 8192;
constexpr int FL_KS  = 8192 + 64 * 132;
constexpr int FL_VS  = FL_KS + 64 * 68;
constexpr int FL_SMEM_FLOATS = FL_VS + 64 * 68;
constexpr int FL_SMEM_BYTES  = FL_SMEM_FLOATS * 4;

__global__ void __launch_bounds__(256) flash2_k(
    const float* __restrict__ Q, const float* __restrict__ K,
    const float* __restrict__ V, float* __restrict__ O)
{
    extern __shared__ float sm[];
    float* Qts = sm + FL_QTS;
    float* Ps  = sm + FL_PS;
    float* Ks  = sm + FL_KS;
    float* Vs  = sm + FL_VS;

    const int qt = blockIdx.x, h = blockIdx.y, b = blockIdx.z;
    const int t  = threadIdx.x;
    const int tx = t & 15, ty = t >> 4;

    // ---- load Q tile transposed & pre-scaled: Qts[d][q] ----
    {
        const int r  = t >> 1;
        const int dq = (t & 1) * 32;
        const float* src = Q + ((size_t)(b * Ss + qt * 128 + r)) * Dd + h * HD + dq;
#pragma unroll
        for (int i = 0; i < 8; i++) {
            float4 v = *(const float4*)(src + i * 4);
            const int d0 = dq + i * 4;
            Qts[(d0 + 0) * 128 + r] = v.x * SCALE;
            Qts[(d0 + 1) * 128 + r] = v.y * SCALE;
            Qts[(d0 + 2) * 128 + r] = v.z * SCALE;
            Qts[(d0 + 3) * 128 + r] = v.w * SCALE;
        }
    }

    float acc[8][4] = {};
    float m_run[8], l_run[8];
#pragma unroll
    for (int i = 0; i < 8; i++) { m_run[i] = -INFINITY; l_run[i] = 0.f; }

    for (int k0 = 0; k0 < Ss; k0 += 64) {
        __syncthreads();   // previous PV reads of Ps/Ks/Vs done

        // ---- load K transposed: Ks[d][k] ----
        {
            const int kx = t & 63;
            const int dq = (t >> 6) * 16;
            const float* src = K + ((size_t)(b * Ss + k0 + kx)) * Dd + h * HD + dq;
#pragma unroll
            for (int i = 0; i < 4; i++) {
                float4 v = *(const float4*)(src + i * 4);
                const int d0 = dq + i * 4;
                Ks[(d0 + 0) * 68 + kx] = v.x;
                Ks[(d0 + 1) * 68 + kx] = v.y;
                Ks[(d0 + 2) * 68 + kx] = v.z;
                Ks[(d0 + 3) * 68 + kx] = v.w;
            }
        }
        // ---- load V row-major: Vs[k][d] ----
        {
            const int kx = t >> 2;
            const int dq = (t & 3) * 16;
            const float* src = V + ((size_t)(b * Ss + k0 + kx)) * Dd + h * HD + dq;
#pragma unroll
            for (int i = 0; i < 4; i++)
                *(float4*)&Vs[kx * 68 + dq + i * 4] = *(const float4*)(src + i * 4);
        }
        __syncthreads();

        // ---- S = Q K^T (microtile 8q x 4k) ----
        float sreg[8][4] = {};
#pragma unroll 8
        for (int kk = 0; kk < 64; kk++) {
            float a[8], bb[4];
            *(float4*)(a)     = *(const float4*)&Qts[kk * 128 + ty * 8];
            *(float4*)(a + 4) = *(const float4*)&Qts[kk * 128 + ty * 8 + 4];
            *(float4*)(bb)    = *(const float4*)&Ks[kk * 68 + tx * 4];
#pragma unroll
            for (int i = 0; i < 8; i++)
#pragma unroll
                for (int j = 0; j < 4; j++) sreg[i][j] += a[i] * bb[j];
        }

        // ---- online softmax (row state replicated across 16 tx lanes) ----
#pragma unroll
        for (int i = 0; i < 8; i++) {
            float mt = fmaxf(fmaxf(sreg[i][0], sreg[i][1]),
                             fmaxf(sreg[i][2], sreg[i][3]));
#pragma unroll
            for (int o = 1; o < 16; o <<= 1)
                mt = fmaxf(mt, __shfl_xor_sync(0xffffffffu, mt, o));
            const float mn = fmaxf(m_run[i], mt);
            const float al = __expf(m_run[i] - mn);
            m_run[i] = mn;
            float lsum = 0.f;
#pragma unroll
            for (int j = 0; j < 4; j++) {
                const float p = __expf(sreg[i][j] - mn);
                Ps[(tx * 4 + j) * 132 + ty * 8 + i] = p;
                lsum += p;
            }
#pragma unroll
            for (int o = 1; o < 16; o <<= 1)
                lsum += __shfl_xor_sync(0xffffffffu, lsum, o);
            l_run[i] = l_run[i] * al + lsum;
#pragma unroll
            for (int j = 0; j < 4; j++) acc[i][j] *= al;
        }
        __syncthreads();

        // ---- O += P V (microtile 8q x 4d) ----
#pragma unroll 8
        for (int kk = 0; kk < 64; kk++) {
            float a[8], bb[4];
            *(float4*)(a)     = *(const float4*)&Ps[kk * 132 + ty * 8];
            *(float4*)(a + 4) = *(const float4*)&Ps[kk * 132 + ty * 8 + 4];
            *(float4*)(bb)    = *(const float4*)&Vs[kk * 68 + tx * 4];
#pragma unroll
            for (int i = 0; i < 8; i++)
#pragma unroll
                for (int j = 0; j < 4; j++) acc[i][j] += a[i] * bb[j];
        }
    }

    // ---- epilogue ----
#pragma unroll
    for (int i = 0; i < 8; i++) {
        const float inv = 1.f / l_run[i];
        float4 o4;
        o4.x = acc[i][0] * inv; o4.y = acc[i][1] * inv;
        o4.z = acc[i][2] * inv; o4.w = acc[i][3] * inv;
        *(float4*)(O + ((size_t)(b * Ss + qt * 128 + ty * 8 + i)) * Dd
                     + h * HD + tx * 4) = o4;
    }
}

// ---------------- local banded attention: warp per (b,h,q) ----------------
__global__ void __launch_bounds__(128) local_attn_k(
    const float* __restrict__ Q, const float* __restrict__ K,
    const float* __restrict__ V, float* __restrict__ O)
{
    const int wid = threadIdx.x >> 5, lane = threadIdx.x & 31;
    const int gw = blockIdx.x * 4 + wid;        // ((b*H + h)*S + q)
    const int q = gw & (Ss - 1);
    const int bh = gw / Ss;
    const int h = bh & (Hh - 1);
    const int b = bh / Hh;

    __shared__ float sc[4][80];

    const float* qp = Q + ((size_t)(b * Ss + q)) * Dd + h * HD;
    const float q0 = qp[lane] * SCALE;
    const float q1 = qp[lane + 32] * SCALE;

    const int jlo = max(0, q - 32), jhi = min(Ss - 1, q + 32);
    const int n = jhi - jlo + 1;

    float m = -INFINITY;
    for (int j = jlo; j <= jhi; j++) {
        const float* kp = K + ((size_t)(b * Ss + j)) * Dd + h * HD;
        float s = q0 * kp[lane] + q1 * kp[lane + 32];
#pragma unroll
        for (int o = 16; o; o >>= 1) s += __shfl_xor_sync(0xffffffffu, s, o);
        if (!lane) sc[wid][j - jlo] = s;
        m = fmaxf(m, s);
    }
    __syncwarp();

    float l = 0.f;
    for (int idx = lane; idx < n; idx += 32) {
        float p = __expf(sc[wid][idx] - m);
        sc[wid][idx] = p;
        l += p;
    }
#pragma unroll
    for (int o = 16; o; o >>= 1) l += __shfl_xor_sync(0xffffffffu, l, o);
    __syncwarp();

    float a0 = 0.f, a1 = 0.f;
    for (int j = jlo; j <= jhi; j++) {
        const float p = sc[wid][j - jlo];
        const float* vp = V + ((size_t)(b * Ss + j)) * Dd + h * HD;
        a0 += p * vp[lane];
        a1 += p * vp[lane + 32];
    }
    const float inv = 1.f / l;
    float* op = O + ((size_t)(b * Ss + q)) * Dd + h * HD;
    op[lane] = a0 * inv;
    op[lane + 32] = a1 * inv;
}

// ---------------- LayerNorm kernels (row = 512, block = 128) ----------------
__global__ void __launch_bounds__(128) ln_add_k(
    const float* __restrict__ A, const float* __restrict__ R,
    const float* __restrict__ g, const float* __restrict__ be,
    float* __restrict__ O)
{
    const int row = blockIdx.x, t = threadIdx.x;
    const size_t base = (size_t)row * Dd + t * 4;
    float4 a = *(const float4*)(A + base);
    float4 r = *(const float4*)(R + base);
    float x[4] = {a.x + r.x, a.y + r.y, a.z + r.z, a.w + r.w};

    float s = x[0] + x[1] + x[2] + x[3];
    float ss = x[0]*x[0] + x[1]*x[1] + x[2]*x[2] + x[3]*x[3];
    __shared__ float sh1[4], sh2[4];
#pragma unroll
    for (int o = 16; o; o >>= 1) {
        s  += __shfl_xor_sync(0xffffffffu, s, o);
        ss += __shfl_xor_sync(0xffffffffu, ss, o);
    }
    if (!(t & 31)) { sh1[t >> 5] = s; sh2[t >> 5] = ss; }
    __syncthreads();
    s  = sh1[0] + sh1[1] + sh1[2] + sh1[3];
    ss = sh2[0] + sh2[1] + sh2[2] + sh2[3];

    const float mean = s * (1.f / Dd);
    const float var = ss * (1.f / Dd) - mean * mean;
    const float rs = rsqrtf(var + 1e-5f);
    float4 gg = *(const float4*)(g + t * 4);
    float4 bb = *(const float4*)(be + t * 4);
    float4 o4;
    o4.x = (x[0] - mean) * rs * gg.x + bb.x;
    o4.y = (x[1] - mean) * rs * gg.y + bb.y;
    o4.z = (x[2] - mean) * rs * gg.z + bb.z;
    o4.w = (x[3] - mean) * rs * gg.w + bb.w;
    *(float4*)(O + base) = o4;
}

// h3 = LN( LN(A+R, g2,b2), g3,b3 )  — two LNs fused
__global__ void __launch_bounds__(128) ln_add_ln_k(
    const float* __restrict__ A, const float* __restrict__ R,
    const float* __restrict__ g2, const float* __restrict__ b2,
    const float* __restrict__ g3, const float* __restrict__ b3,
    float* __restrict__ O)
{
    const int row = blockIdx.x, t = threadIdx.x;
    const size_t base = (size_t)row * Dd + t * 4;
    float4 a = *(const float4*)(A + base);
    float4 r = *(const float4*)(R + base);
    float x[4] = {a.x + r.x, a.y + r.y, a.z + r.z, a.w + r.w};

    __shared__ float sh1[4], sh2[4];
    float s = x[0] + x[1] + x[2] + x[3];
    float ss = x[0]*x[0] + x[1]*x[1] + x[2]*x[2] + x[3]*x[3];
#pragma unroll
    for (int o = 16; o; o >>= 1) {
        s  += __shfl_xor_sync(0xffffffffu, s, o);
        ss += __shfl_xor_sync(0xffffffffu, ss, o);
    }
    if (!(t & 31)) { sh1[t >> 5] = s; sh2[t >> 5] = ss; }
    __syncthreads();
    s  = sh1[0] + sh1[1] + sh1[2] + sh1[3];
    ss = sh2[0] + sh2[1] + sh2[2] + sh2[3];
    float mean = s * (1.f / Dd);
    float var = ss * (1.f / Dd) - mean * mean;
    float rs = rsqrtf(var + 1e-5f);

    float4 gg = *(const float4*)(g2 + t * 4);
    float4 bb = *(const float4*)(b2 + t * 4);
    float y[4];
    y[0] = (x[0] - mean) * rs * gg.x + bb.x;
    y[1] = (x[1] - mean) * rs * gg.y + bb.y;
    y[2] = (x[2] - mean) * rs * gg.z + bb.z;
    y[3] = (x[3] - mean) * rs * gg.w + bb.w;

    __syncthreads();  // reuse sh1/sh2
    s  = y[0] + y[1] + y[2] + y[3];
    ss = y[0]*y[0] + y[1]*y[1] + y[2]*y[2] + y[3]*y[3];
#pragma unroll
    for (int o = 16; o; o >>= 1) {
        s  += __shfl_xor_sync(0xffffffffu, s, o);
        ss += __shfl_xor_sync(0xffffffffu, ss, o);
    }
    if (!(t & 31)) { sh1[t >> 5] = s; sh2[t >> 5] = ss; }
    __syncthreads();
    s  = sh1[0] + sh1[1] + sh1[2] + sh1[3];
    ss = sh2[0] + sh2[1] + sh2[2] + sh2[3];
    mean = s * (1.f / Dd);
    var = ss * (1.f / Dd) - mean * mean;
    rs = rsqrtf(var + 1e-5f);

    float4 g3v = *(const float4*)(g3 + t * 4);
    float4 b3v = *(const float4*)(b3 + t * 4);
    float4 o4;
    o4.x = (y[0] - mean) * rs * g3v.x + b3v.x;
    o4.y = (y[1] - mean) * rs * g3v.y + b3v.y;
    o4.z = (y[2] - mean) * rs * g3v.z + b3v.z;
    o4.w = (y[3] - mean) * rs * g3v.w + b3v.w;
    *(float4*)(O + base) = o4;
}

// ---------------- mean pool over S (deterministic 2-stage) ----------------
__global__ void __launch_bounds__(128) colmean_part_k(const float* __restrict__ X,
                                                      float* __restrict__ PP)
{
    const int b = blockIdx.x >> 2;
    const int d = (blockIdx.x & 3) * 128 + threadIdx.x;
    const int sc = blockIdx.y;  // 16 chunks of 128
    float s = 0.f;
    for (int j = sc * 128; j < sc * 128 + 128; j++)
        s += X[((size_t)(b * Ss + j)) * Dd + d];
    PP[((size_t)sc * Bb + b) * Dd + d] = s;
}

__global__ void __launch_bounds__(128) colmean_fin_k(const float* __restrict__ PP,
                                                     float* __restrict__ P)
{
    const int idx = blockIdx.x * 128 + threadIdx.x;  // 0..B*D-1
    const int b = idx / Dd, d = idx % Dd;
    float s = 0.f;
#pragma unroll
    for (int c = 0; c < 16; c++) s += PP[((size_t)c * Bb + b) * Dd + d];
    P[idx] = s * (1.f / Ss);
}

// ---------------- final tiny GEMM ----------------
__global__ void __launch_bounds__(128) final_k(const float* __restrict__ P,
                                               const float* __restrict__ Wt,
                                               const float* __restrict__ bias,
                                               float* __restrict__ out)
{
    const int b = blockIdx.x, o = threadIdx.x;
    float s = bias[o];
    for (int d = 0; d < Dd; d++) s += P[b * Dd + d] * Wt[d * DOUT + o];
    out[b * DOUT + o] = s;
}

// ---------------- launch ----------------
extern "C" void kernel_launch(void* const* d_in, const int* in_sizes, int n_in,
                              void* d_out, int out_size)
{
    const float* x      = (const float*)d_in[0];
    const float* pos    = (const float*)d_in[1];
    const float* win_w  = (const float*)d_in[2];
    const float* win_b  = (const float*)d_in[3];
    const float* l_wqkv = (const float*)d_in[4];
    const float* l_bqkv = (const float*)d_in[5];
    const float* l_wo   = (const float*)d_in[6];
    const float* l_bo   = (const float*)d_in[7];
    const float* g_wqkv = (const float*)d_in[8];
    const float* g_bqkv = (const float*)d_in[9];
    const float* g_wo   = (const float*)d_in[10];
    const float* g_bo   = (const float*)d_in[11];
    const float* gate_w = (const float*)d_in[12];
    const float* gate_b = (const float*)d_in[13];
    const float* ffn_w1 = (const float*)d_in[14];
    const float* ffn_b1 = (const float*)d_in[15];
    const float* ffn_w2 = (const float*)d_in[16];
    const float* ffn_b2 = (const float*)d_in[17];
    const float* n1_g   = (const float*)d_in[18];
    const float* n1_b   = (const float*)d_in[19];
    const float* n2_g   = (const float*)d_in[20];
    const float* n2_b   = (const float*)d_in[21];
    const float* n3_g   = (const float*)d_in[22];
    const float* n3_b   = (const float*)d_in[23];
    const float* out_w  = (const float*)d_in[24];
    const float* out_b  = (const float*)d_in[25];

    float* sp = nullptr;
    cudaGetSymbolAddress((void**)&sp, g_scratch);
    float* bH   = sp + O_H;
    float* bQ   = sp + O_Q;
    float* bK   = sp + O_K;
    float* bV   = sp + O_V;
    float* bAO  = sp + O_AO;
    float* bLOC = sp + O_LOC;
    float* bGLO = sp + O_GLO;
    float* bFUS = sp + O_FUS;
    float* bH1  = sp + O_H1;
    float* bFFN = sp + O_FFN;
    float* bH3  = sp + O_H3;
    float* bT1  = sp + O_T1;
    float* bPP  = sp + O_PP;
    float* bP   = sp + O_P;

    static bool attr_set = false;
    if (!attr_set) {
        cudaFuncSetAttribute(flash2_k, cudaFuncAttributeMaxDynamicSharedMemorySize,
                             FL_SMEM_BYTES);
        attr_set = true;
    }

    const dim3 blk(256);
    const dim3 gD(Dd / 128, BS / 128);        // N=512 GEMMs
    const dim3 gD2(2 * Dd / 128, BS / 128);   // N=1024 GEMM

    // 1. h = x @ win_w + win_b + pos
    gemm128_k<1><<<gD, blk>>>(x, nullptr, DIN, 0, win_w, win_b, pos, nullptr,
                              bH, BS, Dd, DIN);

    // 2. local QKV
    float* qkv[3] = {bQ, bK, bV};
    for (int i = 0; i < 3; i++)
        gemm128_k<0><<<gD, blk>>>(bH, nullptr, Dd, 0, l_wqkv + (size_t)i * Dd * Dd,
                                  l_bqkv + i * Dd, nullptr, nullptr, qkv[i], BS, Dd, Dd);

    // 3. local banded attention
    local_attn_k<<<(Bb * Hh * Ss) / 4, 128>>>(bQ, bK, bV, bAO);

    // 4. local_out = attn_o @ l_wo + l_bo
    gemm128_k<0><<<gD, blk>>>(bAO, nullptr, Dd, 0, l_wo, l_bo, nullptr, nullptr,
                              bLOC, BS, Dd, Dd);

    // 5. global QKV
    for (int i = 0; i < 3; i++)
        gemm128_k<0><<<gD, blk>>>(bH, nullptr, Dd, 0, g_wqkv + (size_t)i * Dd * Dd,
                                  g_bqkv + i * Dd, nullptr, nullptr, qkv[i], BS, Dd, Dd);

    // 6. global flash attention
    flash2_k<<<dim3(Ss / 128, Hh, Bb), 256, FL_SMEM_BYTES>>>(bQ, bK, bV, bAO);

    // 7. global_out
    gemm128_k<0><<<gD, blk>>>(bAO, nullptr, Dd, 0, g_wo, g_bo, nullptr, nullptr,
                              bGLO, BS, Dd, Dd);

    // 8. gate GEMM fused with blend
    gemm128_k<3><<<gD, blk>>>(bLOC, bGLO, Dd, Dd, gate_w, gate_b, bLOC, bGLO,
                              bFUS, BS, Dd, 2 * Dd);

    // 9. h1 = LN(h + fused)
    ln_add_k<<<BS, 128>>>(bH, bFUS, n1_g, n1_b, bH1);

    // 10. FFN
    gemm128_k<2><<<gD2, blk>>>(bH1, nullptr, Dd, 0, ffn_w1, ffn_b1, nullptr, nullptr,
                               bT1, BS, 2 * Dd, Dd);
    gemm128_k<0><<<gD, blk>>>(bT1, nullptr, 2 * Dd, 0, ffn_w2, ffn_b2, nullptr, nullptr,
                              bFFN, BS, Dd, 2 * Dd);

    // 11. h3 = LN(LN(h1 + ffn))
    ln_add_ln_k<<<BS, 128>>>(bH1, bFFN, n2_g, n2_b, n3_g, n3_b, bH3);

    // 12. mean-pool over S, then final projection
    colmean_part_k<<<dim3(Bb * 4, 16), 128>>>(bH3, bPP);
    colmean_fin_k<<<(Bb * Dd) / 128, 128>>>(bPP, bP);
    final_k<<<Bb, DOUT>>>(bP, out_w, out_b, (float*)d_out);

    (void)in_sizes; (void)n_in; (void)out_size;
}

// round 3
// speedup vs baseline: 2.1238x; 1.4735x over previous
#include <cuda_runtime.h>
#include <math.h>
#include <stdint.h>

// ---------------- problem constants (hardcoded) ----------------
constexpr int   Bb   = 4;
constexpr int   Ss   = 2048;
constexpr int   DIN  = 256;
constexpr int   Dd   = 512;
constexpr int   Hh   = 8;
constexpr int   DOUT = 128;
constexpr int   HD   = 64;       // Dd / Hh
constexpr int   BS   = Bb * Ss;  // 8192 rows
constexpr float SCALE = 0.125f;  // 1/sqrt(64)

// ---------------- scratch (static device memory; no allocs) ----------------
constexpr size_t NBD  = (size_t)BS * Dd;
constexpr size_t O_H   = 0;
constexpr size_t O_Q   = 1 * NBD;
constexpr size_t O_K   = 2 * NBD;
constexpr size_t O_V   = 3 * NBD;
constexpr size_t O_AO  = 4 * NBD;
constexpr size_t O_LOC = 5 * NBD;
constexpr size_t O_GLO = 6 * NBD;
constexpr size_t O_FUS = 7 * NBD;
constexpr size_t O_H1  = 8 * NBD;
constexpr size_t O_FFN = 9 * NBD;
constexpr size_t O_H3  = 10 * NBD;
constexpr size_t O_T1  = 11 * NBD;              // 2*NBD wide (FFN hidden)
constexpr size_t O_PP  = 13 * NBD;
constexpr size_t O_P   = 13 * NBD + (size_t)16 * Bb * Dd;
constexpr size_t SCRATCH_FLOATS = O_P + (size_t)Bb * Dd;

__device__ float g_scratch[SCRATCH_FLOATS];

// ---------------- helpers: tf32 convert + mma ----------------
__device__ __forceinline__ float cvt_tf32(float x) {
    uint32_t u;
    asm("cvt.rna.tf32.f32 %0, %1;" : "=r"(u) : "f"(x));
    return __uint_as_float(u);
}

__device__ __forceinline__ void mma_tf32(float c[4], const uint32_t a[4],
                                         const uint32_t b[2]) {
    asm volatile(
        "mma.sync.aligned.m16n8k8.row.col.f32.tf32.tf32.f32 "
        "{%0,%1,%2,%3},{%4,%5,%6,%7},{%8,%9},{%0,%1,%2,%3};\n"
        : "+f"(c[0]), "+f"(c[1]), "+f"(c[2]), "+f"(c[3])
        : "r"(a[0]), "r"(a[1]), "r"(a[2]), "r"(a[3]), "r"(b[0]), "r"(b[1]));
}

// ---------------- TF32 tensor-core GEMM, 128x128 tile, fused epilogues -----
// C[M,N] = A[M,K] @ W[K,N] (+epilogue). A row-major lda, W row-major N.
// MODE 0: +bias
// MODE 1: +bias + pos[(row%S)*N + col]
// MODE 2: relu(+bias)
// MODE 3: A = concat(A, A2) along K (split at KA);
//         g = tanh(relu(acc+bias)); C = g*p1 + (1-g)*p2
// 256 threads = 8 warps (2m x 4n), each warp 64x32 via m16n8k8.
// Double-buffered smem, rows padded to 136 floats (conflict-free frag loads).
template <int MODE>
__global__ void __launch_bounds__(256) gemm_tc_k(
    const float* __restrict__ A, const float* __restrict__ A2, int lda, int KA,
    const float* __restrict__ W, const float* __restrict__ bias,
    const float* __restrict__ p1, const float* __restrict__ p2,
    float* __restrict__ C, int M, int N, int K)
{
    __shared__ float As[2][16][136];   // [k][m]
    __shared__ float Bs[2][16][136];   // [k][n]

    const int t  = threadIdx.x;
    const int n0 = blockIdx.x * 128, m0 = blockIdx.y * 128;

    const int lane = t & 31, w = t >> 5;
    const int wm = w & 1, wn = w >> 1;          // 2 x 4 warp grid
    const int gid = lane >> 2, tig = lane & 3;
    const int mw = wm * 64, nw = wn * 32;

    const int amr = t >> 1;           // A loader: m row 0..127
    const int akc = (t & 1) * 8;      // A loader: k col 0 or 8
    const int bkr = t >> 4;           // B loader: k row 0..15
    const int bnc = (t & 15) * 8;     // B loader: n col 0..120

    float acc[4][4][4] = {};
    float4 pa0, pa1, pb0, pb1;

    // ---- prefetch tile 0 ----
    {
        const float* Asrc = A;
        int kk0 = 0;
        if (MODE == 3 && 0 >= KA) { Asrc = A2; kk0 = -KA; }
        pa0 = *(const float4*)(Asrc + (size_t)(m0 + amr) * lda + kk0 + akc);
        pa1 = *(const float4*)(Asrc + (size_t)(m0 + amr) * lda + kk0 + akc + 4);
        pb0 = *(const float4*)(W + (size_t)bkr * N + n0 + bnc);
        pb1 = *(const float4*)(W + (size_t)bkr * N + n0 + bnc + 4);
    }
    // store to buf 0
    {
        float av[8] = {pa0.x, pa0.y, pa0.z, pa0.w, pa1.x, pa1.y, pa1.z, pa1.w};
#pragma unroll
        for (int j = 0; j < 8; j++) As[0][akc + j][amr] = cvt_tf32(av[j]);
        float4 c0, c1;
        c0.x = cvt_tf32(pb0.x); c0.y = cvt_tf32(pb0.y);
        c0.z = cvt_tf32(pb0.z); c0.w = cvt_tf32(pb0.w);
        c1.x = cvt_tf32(pb1.x); c1.y = cvt_tf32(pb1.y);
        c1.z = cvt_tf32(pb1.z); c1.w = cvt_tf32(pb1.w);
        *(float4*)&Bs[0][bkr][bnc]     = c0;
        *(float4*)&Bs[0][bkr][bnc + 4] = c1;
    }
    __syncthreads();

    int buf = 0;
    for (int k0 = 0; k0 < K; k0 += 16) {
        const int kn = k0 + 16;
        const bool has_next = kn < K;
        if (has_next) {
            const float* Asrc = A;
            int kk0 = kn;
            if (MODE == 3 && kn >= KA) { Asrc = A2; kk0 = kn - KA; }
            pa0 = *(const float4*)(Asrc + (size_t)(m0 + amr) * lda + kk0 + akc);
            pa1 = *(const float4*)(Asrc + (size_t)(m0 + amr) * lda + kk0 + akc + 4);
            pb0 = *(const float4*)(W + (size_t)(kn + bkr) * N + n0 + bnc);
            pb1 = *(const float4*)(W + (size_t)(kn + bkr) * N + n0 + bnc + 4);
        }

        // ---- compute from smem[buf] ----
#pragma unroll
        for (int kk = 0; kk < 16; kk += 8) {
            uint32_t af[4][4], bf[4][2];
#pragma unroll
            for (int mt = 0; mt < 4; mt++) {
                const int m = mw + mt * 16 + gid;
                af[mt][0] = __float_as_uint(As[buf][kk + tig][m]);
                af[mt][1] = __float_as_uint(As[buf][kk + tig][m + 8]);
                af[mt][2] = __float_as_uint(As[buf][kk + tig + 4][m]);
                af[mt][3] = __float_as_uint(As[buf][kk + tig + 4][m + 8]);
            }
#pragma unroll
            for (int nt = 0; nt < 4; nt++) {
                const int n = nw + nt * 8 + gid;
                bf[nt][0] = __float_as_uint(Bs[buf][kk + tig][n]);
                bf[nt][1] = __float_as_uint(Bs[buf][kk + tig + 4][n]);
            }
#pragma unroll
            for (int mt = 0; mt < 4; mt++)
#pragma unroll
                for (int nt = 0; nt < 4; nt++)
                    mma_tf32(acc[mt][nt], af[mt], bf[nt]);
        }

        if (has_next) {
            const int nb = buf ^ 1;
            float av[8] = {pa0.x, pa0.y, pa0.z, pa0.w, pa1.x, pa1.y, pa1.z, pa1.w};
#pragma unroll
            for (int j = 0; j < 8; j++) As[nb][akc + j][amr] = cvt_tf32(av[j]);
            float4 c0, c1;
            c0.x = cvt_tf32(pb0.x); c0.y = cvt_tf32(pb0.y);
            c0.z = cvt_tf32(pb0.z); c0.w = cvt_tf32(pb0.w);
            c1.x = cvt_tf32(pb1.x); c1.y = cvt_tf32(pb1.y);
            c1.z = cvt_tf32(pb1.z); c1.w = cvt_tf32(pb1.w);
            *(float4*)&Bs[nb][bkr][bnc]     = c0;
            *(float4*)&Bs[nb][bkr][bnc + 4] = c1;
        }
        __syncthreads();
        buf ^= 1;
    }

    // ---- epilogue ----
#pragma unroll
    for (int mt = 0; mt < 4; mt++) {
#pragma unroll
        for (int half = 0; half < 2; half++) {
            const int row = m0 + mw + mt * 16 + gid + half * 8;
#pragma unroll
            for (int nt = 0; nt < 4; nt++) {
                const int col = n0 + nw + nt * 8 + tig * 2;
                float v0 = acc[mt][nt][half * 2 + 0] + bias[col];
                float v1 = acc[mt][nt][half * 2 + 1] + bias[col + 1];
                if (MODE == 1) {
                    const size_t pr = (size_t)(row & (Ss - 1)) * N + col;
                    v0 += p1[pr]; v1 += p1[pr + 1];
                }
                if (MODE == 2) { v0 = fmaxf(v0, 0.f); v1 = fmaxf(v1, 0.f); }
                if (MODE == 3) {
                    const size_t pr = (size_t)row * N + col;
                    float g0 = tanhf(fmaxf(v0, 0.f));
                    float g1 = tanhf(fmaxf(v1, 0.f));
                    v0 = g0 * p1[pr] + (1.f - g0) * p2[pr];
                    v1 = g1 * p1[pr + 1] + (1.f - g1) * p2[pr + 1];
                }
                float2 o2; o2.x = v0; o2.y = v1;
                *(float2*)(C + (size_t)row * N + col) = o2;
            }
        }
    }
}

// ---------------- global attention: GEMM-structured fp32 flash -------------
constexpr int FL_QTS = 0;
constexpr int FL_PS  = 8192;
constexpr int FL_KS  = 8192 + 64 * 132;
constexpr int FL_VS  = FL_KS + 64 * 68;
constexpr int FL_SMEM_FLOATS = FL_VS + 64 * 68;
constexpr int FL_SMEM_BYTES  = FL_SMEM_FLOATS * 4;

__global__ void __launch_bounds__(256) flash2_k(
    const float* __restrict__ Q, const float* __restrict__ K,
    const float* __restrict__ V, float* __restrict__ O)
{
    extern __shared__ float sm[];
    float* Qts = sm + FL_QTS;
    float* Ps  = sm + FL_PS;
    float* Ks  = sm + FL_KS;
    float* Vs  = sm + FL_VS;

    const int qt = blockIdx.x, h = blockIdx.y, b = blockIdx.z;
    const int t  = threadIdx.x;
    const int tx = t & 15, ty = t >> 4;

    {
        const int r  = t >> 1;
        const int dq = (t & 1) * 32;
        const float* src = Q + ((size_t)(b * Ss + qt * 128 + r)) * Dd + h * HD + dq;
#pragma unroll
        for (int i = 0; i < 8; i++) {
            float4 v = *(const float4*)(src + i * 4);
            const int d0 = dq + i * 4;
            Qts[(d0 + 0) * 128 + r] = v.x * SCALE;
            Qts[(d0 + 1) * 128 + r] = v.y * SCALE;
            Qts[(d0 + 2) * 128 + r] = v.z * SCALE;
            Qts[(d0 + 3) * 128 + r] = v.w * SCALE;
        }
    }

    float acc[8][4] = {};
    float m_run[8], l_run[8];
#pragma unroll
    for (int i = 0; i < 8; i++) { m_run[i] = -INFINITY; l_run[i] = 0.f; }

    for (int k0 = 0; k0 < Ss; k0 += 64) {
        __syncthreads();

        {
            const int kx = t & 63;
            const int dq = (t >> 6) * 16;
            const float* src = K + ((size_t)(b * Ss + k0 + kx)) * Dd + h * HD + dq;
#pragma unroll
            for (int i = 0; i < 4; i++) {
                float4 v = *(const float4*)(src + i * 4);
                const int d0 = dq + i * 4;
                Ks[(d0 + 0) * 68 + kx] = v.x;
                Ks[(d0 + 1) * 68 + kx] = v.y;
                Ks[(d0 + 2) * 68 + kx] = v.z;
                Ks[(d0 + 3) * 68 + kx] = v.w;
            }
        }
        {
            const int kx = t >> 2;
            const int dq = (t & 3) * 16;
            const float* src = V + ((size_t)(b * Ss + k0 + kx)) * Dd + h * HD + dq;
#pragma unroll
            for (int i = 0; i < 4; i++)
                *(float4*)&Vs[kx * 68 + dq + i * 4] = *(const float4*)(src + i * 4);
        }
        __syncthreads();

        float sreg[8][4] = {};
#pragma unroll 8
        for (int kk = 0; kk < 64; kk++) {
            float a[8], bb[4];
            *(float4*)(a)     = *(const float4*)&Qts[kk * 128 + ty * 8];
            *(float4*)(a + 4) = *(const float4*)&Qts[kk * 128 + ty * 8 + 4];
            *(float4*)(bb)    = *(const float4*)&Ks[kk * 68 + tx * 4];
#pragma unroll
            for (int i = 0; i < 8; i++)
#pragma unroll
                for (int j = 0; j < 4; j++) sreg[i][j] += a[i] * bb[j];
        }

#pragma unroll
        for (int i = 0; i < 8; i++) {
            float mt = fmaxf(fmaxf(sreg[i][0], sreg[i][1]),
                             fmaxf(sreg[i][2], sreg[i][3]));
#pragma unroll
            for (int o = 1; o < 16; o <<= 1)
                mt = fmaxf(mt, __shfl_xor_sync(0xffffffffu, mt, o));
            const float mn = fmaxf(m_run[i], mt);
            const float al = __expf(m_run[i] - mn);
            m_run[i] = mn;
            float lsum = 0.f;
#pragma unroll
            for (int j = 0; j < 4; j++) {
                const float p = __expf(sreg[i][j] - mn);
                Ps[(tx * 4 + j) * 132 + ty * 8 + i] = p;
                lsum += p;
            }
#pragma unroll
            for (int o = 1; o < 16; o <<= 1)
                lsum += __shfl_xor_sync(0xffffffffu, lsum, o);
            l_run[i] = l_run[i] * al + lsum;
#pragma unroll
            for (int j = 0; j < 4; j++) acc[i][j] *= al;
        }
        __syncthreads();

#pragma unroll 8
        for (int kk = 0; kk < 64; kk++) {
            float a[8], bb[4];
            *(float4*)(a)     = *(const float4*)&Ps[kk * 132 + ty * 8];
            *(float4*)(a + 4) = *(const float4*)&Ps[kk * 132 + ty * 8 + 4];
            *(float4*)(bb)    = *(const float4*)&Vs[kk * 68 + tx * 4];
#pragma unroll
            for (int i = 0; i < 8; i++)
#pragma unroll
                for (int j = 0; j < 4; j++) acc[i][j] += a[i] * bb[j];
        }
    }

#pragma unroll
    for (int i = 0; i < 8; i++) {
        const float inv = 1.f / l_run[i];
        float4 o4;
        o4.x = acc[i][0] * inv; o4.y = acc[i][1] * inv;
        o4.z = acc[i][2] * inv; o4.w = acc[i][3] * inv;
        *(float4*)(O + ((size_t)(b * Ss + qt * 128 + ty * 8 + i)) * Dd
                     + h * HD + tx * 4) = o4;
    }
}

// ---------------- local banded attention: warp per (b,h,q) ----------------
__global__ void __launch_bounds__(128) local_attn_k(
    const float* __restrict__ Q, const float* __restrict__ K,
    const float* __restrict__ V, float* __restrict__ O)
{
    const int wid = threadIdx.x >> 5, lane = threadIdx.x & 31;
    const int gw = blockIdx.x * 4 + wid;
    const int q = gw & (Ss - 1);
    const int bh = gw / Ss;
    const int h = bh & (Hh - 1);
    const int b = bh / Hh;

    __shared__ float sc[4][80];

    const float* qp = Q + ((size_t)(b * Ss + q)) * Dd + h * HD;
    const float q0 = qp[lane] * SCALE;
    const float q1 = qp[lane + 32] * SCALE;

    const int jlo = max(0, q - 32), jhi = min(Ss - 1, q + 32);
    const int n = jhi - jlo + 1;

    float m = -INFINITY;
    for (int j = jlo; j <= jhi; j++) {
        const float* kp = K + ((size_t)(b * Ss + j)) * Dd + h * HD;
        float s = q0 * kp[lane] + q1 * kp[lane + 32];
#pragma unroll
        for (int o = 16; o; o >>= 1) s += __shfl_xor_sync(0xffffffffu, s, o);
        if (!lane) sc[wid][j - jlo] = s;
        m = fmaxf(m, s);
    }
    __syncwarp();

    float l = 0.f;
    for (int idx = lane; idx < n; idx += 32) {
        float p = __expf(sc[wid][idx] - m);
        sc[wid][idx] = p;
        l += p;
    }
#pragma unroll
    for (int o = 16; o; o >>= 1) l += __shfl_xor_sync(0xffffffffu, l, o);
    __syncwarp();

    float a0 = 0.f, a1 = 0.f;
    for (int j = jlo; j <= jhi; j++) {
        const float p = sc[wid][j - jlo];
        const float* vp = V + ((size_t)(b * Ss + j)) * Dd + h * HD;
        a0 += p * vp[lane];
        a1 += p * vp[lane + 32];
    }
    const float inv = 1.f / l;
    float* op = O + ((size_t)(b * Ss + q)) * Dd + h * HD;
    op[lane] = a0 * inv;
    op[lane + 32] = a1 * inv;
}

// ---------------- LayerNorm kernels ----------------
__global__ void __launch_bounds__(128) ln_add_k(
    const float* __restrict__ A, const float* __restrict__ R,
    const float* __restrict__ g, const float* __restrict__ be,
    float* __restrict__ O)
{
    const int row = blockIdx.x, t = threadIdx.x;
    const size_t base = (size_t)row * Dd + t * 4;
    float4 a = *(const float4*)(A + base);
    float4 r = *(const float4*)(R + base);
    float x[4] = {a.x + r.x, a.y + r.y, a.z + r.z, a.w + r.w};

    float s = x[0] + x[1] + x[2] + x[3];
    float ss = x[0]*x[0] + x[1]*x[1] + x[2]*x[2] + x[3]*x[3];
    __shared__ float sh1[4], sh2[4];
#pragma unroll
    for (int o = 16; o; o >>= 1) {
        s  += __shfl_xor_sync(0xffffffffu, s, o);
        ss += __shfl_xor_sync(0xffffffffu, ss, o);
    }
    if (!(t & 31)) { sh1[t >> 5] = s; sh2[t >> 5] = ss; }
    __syncthreads();
    s  = sh1[0] + sh1[1] + sh1[2] + sh1[3];
    ss = sh2[0] + sh2[1] + sh2[2] + sh2[3];

    const float mean = s * (1.f / Dd);
    const float var = ss * (1.f / Dd) - mean * mean;
    const float rs = rsqrtf(var + 1e-5f);
    float4 gg = *(const float4*)(g + t * 4);
    float4 bb = *(const float4*)(be + t * 4);
    float4 o4;
    o4.x = (x[0] - mean) * rs * gg.x + bb.x;
    o4.y = (x[1] - mean) * rs * gg.y + bb.y;
    o4.z = (x[2] - mean) * rs * gg.z + bb.z;
    o4.w = (x[3] - mean) * rs * gg.w + bb.w;
    *(float4*)(O + base) = o4;
}

__global__ void __launch_bounds__(128) ln_add_ln_k(
    const float* __restrict__ A, const float* __restrict__ R,
    const float* __restrict__ g2, const float* __restrict__ b2,
    const float* __restrict__ g3, const float* __restrict__ b3,
    float* __restrict__ O)
{
    const int row = blockIdx.x, t = threadIdx.x;
    const size_t base = (size_t)row * Dd + t * 4;
    float4 a = *(const float4*)(A + base);
    float4 r = *(const float4*)(R + base);
    float x[4] = {a.x + r.x, a.y + r.y, a.z + r.z, a.w + r.w};

    __shared__ float sh1[4], sh2[4];
    float s = x[0] + x[1] + x[2] + x[3];
    float ss = x[0]*x[0] + x[1]*x[1] + x[2]*x[2] + x[3]*x[3];
#pragma unroll
    for (int o = 16; o; o >>= 1) {
        s  += __shfl_xor_sync(0xffffffffu, s, o);
        ss += __shfl_xor_sync(0xffffffffu, ss, o);
    }
    if (!(t & 31)) { sh1[t >> 5] = s; sh2[t >> 5] = ss; }
    __syncthreads();
    s  = sh1[0] + sh1[1] + sh1[2] + sh1[3];
    ss = sh2[0] + sh2[1] + sh2[2] + sh2[3];
    float mean = s * (1.f / Dd);
    float var = ss * (1.f / Dd) - mean * mean;
    float rs = rsqrtf(var + 1e-5f);

    float4 gg = *(const float4*)(g2 + t * 4);
    float4 bb = *(const float4*)(b2 + t * 4);
    float y[4];
    y[0] = (x[0] - mean) * rs * gg.x + bb.x;
    y[1] = (x[1] - mean) * rs * gg.y + bb.y;
    y[2] = (x[2] - mean) * rs * gg.z + bb.z;
    y[3] = (x[3] - mean) * rs * gg.w + bb.w;

    __syncthreads();
    s  = y[0] + y[1] + y[2] + y[3];
    ss = y[0]*y[0] + y[1]*y[1] + y[2]*y[2] + y[3]*y[3];
#pragma unroll
    for (int o = 16; o; o >>= 1) {
        s  += __shfl_xor_sync(0xffffffffu, s, o);
        ss += __shfl_xor_sync(0xffffffffu, ss, o);
    }
    if (!(t & 31)) { sh1[t >> 5] = s; sh2[t >> 5] = ss; }
    __syncthreads();
    s  = sh1[0] + sh1[1] + sh1[2] + sh1[3];
    ss = sh2[0] + sh2[1] + sh2[2] + sh2[3];
    mean = s * (1.f / Dd);
    var = ss * (1.f / Dd) - mean * mean;
    rs = rsqrtf(var + 1e-5f);

    float4 g3v = *(const float4*)(g3 + t * 4);
    float4 b3v = *(const float4*)(b3 + t * 4);
    float4 o4;
    o4.x = (y[0] - mean) * rs * g3v.x + b3v.x;
    o4.y = (y[1] - mean) * rs * g3v.y + b3v.y;
    o4.z = (y[2] - mean) * rs * g3v.z + b3v.z;
    o4.w = (y[3] - mean) * rs * g3v.w + b3v.w;
    *(float4*)(O + base) = o4;
}

// ---------------- mean pool over S (deterministic 2-stage) ----------------
__global__ void __launch_bounds__(128) colmean_part_k(const float* __restrict__ X,
                                                      float* __restrict__ PP)
{
    const int b = blockIdx.x >> 2;
    const int d = (blockIdx.x & 3) * 128 + threadIdx.x;
    const int sc = blockIdx.y;
    float s = 0.f;
    for (int j = sc * 128; j < sc * 128 + 128; j++)
        s += X[((size_t)(b * Ss + j)) * Dd + d];
    PP[((size_t)sc * Bb + b) * Dd + d] = s;
}

__global__ void __launch_bounds__(128) colmean_fin_k(const float* __restrict__ PP,
                                                     float* __restrict__ P)
{
    const int idx = blockIdx.x * 128 + threadIdx.x;
    const int b = idx / Dd, d = idx % Dd;
    float s = 0.f;
#pragma unroll
    for (int c = 0; c < 16; c++) s += PP[((size_t)c * Bb + b) * Dd + d];
    P[idx] = s * (1.f / Ss);
}

// ---------------- final tiny GEMM ----------------
__global__ void __launch_bounds__(128) final_k(const float* __restrict__ P,
                                               const float* __restrict__ Wt,
                                               const float* __restrict__ bias,
                                               float* __restrict__ out)
{
    const int b = blockIdx.x, o = threadIdx.x;
    float s = bias[o];
    for (int d = 0; d < Dd; d++) s += P[b * Dd + d] * Wt[d * DOUT + o];
    out[b * DOUT + o] = s;
}

// ---------------- launch ----------------
extern "C" void kernel_launch(void* const* d_in, const int* in_sizes, int n_in,
                              void* d_out, int out_size)
{
    const float* x      = (const float*)d_in[0];
    const float* pos    = (const float*)d_in[1];
    const float* win_w  = (const float*)d_in[2];
    const float* win_b  = (const float*)d_in[3];
    const float* l_wqkv = (const float*)d_in[4];
    const float* l_bqkv = (const float*)d_in[5];
    const float* l_wo   = (const float*)d_in[6];
    const float* l_bo   = (const float*)d_in[7];
    const float* g_wqkv = (const float*)d_in[8];
    const float* g_bqkv = (const float*)d_in[9];
    const float* g_wo   = (const float*)d_in[10];
    const float* g_bo   = (const float*)d_in[11];
    const float* gate_w = (const float*)d_in[12];
    const float* gate_b = (const float*)d_in[13];
    const float* ffn_w1 = (const float*)d_in[14];
    const float* ffn_b1 = (const float*)d_in[15];
    const float* ffn_w2 = (const float*)d_in[16];
    const float* ffn_b2 = (const float*)d_in[17];
    const float* n1_g   = (const float*)d_in[18];
    const float* n1_b   = (const float*)d_in[19];
    const float* n2_g   = (const float*)d_in[20];
    const float* n2_b   = (const float*)d_in[21];
    const float* n3_g   = (const float*)d_in[22];
    const float* n3_b   = (const float*)d_in[23];
    const float* out_w  = (const float*)d_in[24];
    const float* out_b  = (const float*)d_in[25];

    float* sp = nullptr;
    cudaGetSymbolAddress((void**)&sp, g_scratch);
    float* bH   = sp + O_H;
    float* bQ   = sp + O_Q;
    float* bK   = sp + O_K;
    float* bV   = sp + O_V;
    float* bAO  = sp + O_AO;
    float* bLOC = sp + O_LOC;
    float* bGLO = sp + O_GLO;
    float* bFUS = sp + O_FUS;
    float* bH1  = sp + O_H1;
    float* bFFN = sp + O_FFN;
    float* bH3  = sp + O_H3;
    float* bT1  = sp + O_T1;
    float* bPP  = sp + O_PP;
    float* bP   = sp + O_P;

    static bool attr_set = false;
    if (!attr_set) {
        cudaFuncSetAttribute(flash2_k, cudaFuncAttributeMaxDynamicSharedMemorySize,
                             FL_SMEM_BYTES);
        attr_set = true;
    }

    const dim3 blk(256);
    const dim3 gD(Dd / 128, BS / 128);        // N=512 GEMMs
    const dim3 gD2(2 * Dd / 128, BS / 128);   // N=1024 GEMM

    // 1. h = x @ win_w + win_b + pos
    gemm_tc_k<1><<<gD, blk>>>(x, nullptr, DIN, 0, win_w, win_b, pos, nullptr,
                              bH, BS, Dd, DIN);

    // 2. local QKV
    float* qkv[3] = {bQ, bK, bV};
    for (int i = 0; i < 3; i++)
        gemm_tc_k<0><<<gD, blk>>>(bH, nullptr, Dd, 0, l_wqkv + (size_t)i * Dd * Dd,
                                  l_bqkv + i * Dd, nullptr, nullptr, qkv[i], BS, Dd, Dd);

    // 3. local banded attention
    local_attn_k<<<(Bb * Hh * Ss) / 4, 128>>>(bQ, bK, bV, bAO);

    // 4. local_out = attn_o @ l_wo + l_bo
    gemm_tc_k<0><<<gD, blk>>>(bAO, nullptr, Dd, 0, l_wo, l_bo, nullptr, nullptr,
                              bLOC, BS, Dd, Dd);

    // 5. global QKV
    for (int i = 0; i < 3; i++)
        gemm_tc_k<0><<<gD, blk>>>(bH, nullptr, Dd, 0, g_wqkv + (size_t)i * Dd * Dd,
                                  g_bqkv + i * Dd, nullptr, nullptr, qkv[i], BS, Dd, Dd);

    // 6. global flash attention
    flash2_k<<<dim3(Ss / 128, Hh, Bb), 256, FL_SMEM_BYTES>>>(bQ, bK, bV, bAO);

    // 7. global_out
    gemm_tc_k<0><<<gD, blk>>>(bAO, nullptr, Dd, 0, g_wo, g_bo, nullptr, nullptr,
                              bGLO, BS, Dd, Dd);

    // 8. gate GEMM fused with blend
    gemm_tc_k<3><<<gD, blk>>>(bLOC, bGLO, Dd, Dd, gate_w, gate_b, bLOC, bGLO,
                              bFUS, BS, Dd, 2 * Dd);

    // 9. h1 = LN(h + fused)
    ln_add_k<<<BS, 128>>>(bH, bFUS, n1_g, n1_b, bH1);

    // 10. FFN
    gemm_tc_k<2><<<gD2, blk>>>(bH1, nullptr, Dd, 0, ffn_w1, ffn_b1, nullptr, nullptr,
                               bT1, BS, 2 * Dd, Dd);
    gemm_tc_k<0><<<gD, blk>>>(bT1, nullptr, 2 * Dd, 0, ffn_w2, ffn_b2, nullptr, nullptr,
                              bFFN, BS, Dd, 2 * Dd);

    // 11. h3 = LN(LN(h1 + ffn))
    ln_add_ln_k<<<BS, 128>>>(bH1, bFFN, n2_g, n2_b, n3_g, n3_b, bH3);

    // 12. mean-pool over S, then final projection
    colmean_part_k<<<dim3(Bb * 4, 16), 128>>>(bH3, bPP);
    colmean_fin_k<<<(Bb * Dd) / 128, 128>>>(bPP, bP);
    final_k<<<Bb, DOUT>>>(bP, out_w, out_b, (float*)d_out);

    (void)in_sizes; (void)n_in; (void)out_size;
}

// round 4
// speedup vs baseline: 3.0977x; 1.4586x over previous
#include <cuda_runtime.h>
#include <math.h>
#include <stdint.h>

// ---------------- problem constants (hardcoded) ----------------
constexpr int   Bb   = 4;
constexpr int   Ss   = 2048;
constexpr int   DIN  = 256;
constexpr int   Dd   = 512;
constexpr int   Hh   = 8;
constexpr int   DOUT = 128;
constexpr int   HD   = 64;       // Dd / Hh
constexpr int   BS   = Bb * Ss;  // 8192 rows
constexpr float SCALE = 0.125f;  // 1/sqrt(64)

// ---------------- scratch (static device memory; no allocs) ----------------
constexpr size_t NBD  = (size_t)BS * Dd;
constexpr size_t O_H   = 0;
constexpr size_t O_Q   = 1 * NBD;
constexpr size_t O_K   = 2 * NBD;
constexpr size_t O_V   = 3 * NBD;
constexpr size_t O_AO  = 4 * NBD;
constexpr size_t O_LOC = 5 * NBD;
constexpr size_t O_GLO = 6 * NBD;
constexpr size_t O_FUS = 7 * NBD;
constexpr size_t O_H1  = 8 * NBD;
constexpr size_t O_FFN = 9 * NBD;
constexpr size_t O_H3  = 10 * NBD;
constexpr size_t O_T1  = 11 * NBD;              // 2*NBD wide (FFN hidden)
constexpr size_t O_PP  = 13 * NBD;
constexpr size_t O_P   = 13 * NBD + (size_t)16 * Bb * Dd;
constexpr size_t SCRATCH_FLOATS = O_P + (size_t)Bb * Dd;

__device__ float g_scratch[SCRATCH_FLOATS];

// ---------------- helpers: tf32 convert + mma ----------------
__device__ __forceinline__ float cvt_tf32(float x) {
    uint32_t u;
    asm("cvt.rna.tf32.f32 %0, %1;" : "=r"(u) : "f"(x));
    return __uint_as_float(u);
}

__device__ __forceinline__ void mma_tf32(float c[4], const uint32_t a[4],
                                         const uint32_t b[2]) {
    asm volatile(
        "mma.sync.aligned.m16n8k8.row.col.f32.tf32.tf32.f32 "
        "{%0,%1,%2,%3},{%4,%5,%6,%7},{%8,%9},{%0,%1,%2,%3};\n"
        : "+f"(c[0]), "+f"(c[1]), "+f"(c[2]), "+f"(c[3])
        : "r"(a[0]), "r"(a[1]), "r"(a[2]), "r"(a[3]), "r"(b[0]), "r"(b[1]));
}

// ---------------- TF32 tensor-core GEMM, 128x128 tile, fused epilogues -----
// MODE 0: +bias ; MODE 1: +bias+pos ; MODE 2: relu(+bias)
// MODE 3: A=concat(A,A2) on K; g=tanh(relu(acc+bias)); C=g*p1+(1-g)*p2
template <int MODE>
__global__ void __launch_bounds__(256) gemm_tc_k(
    const float* __restrict__ A, const float* __restrict__ A2, int lda, int KA,
    const float* __restrict__ W, const float* __restrict__ bias,
    const float* __restrict__ p1, const float* __restrict__ p2,
    float* __restrict__ C, int M, int N, int K)
{
    __shared__ float As[2][16][136];   // [k][m]
    __shared__ float Bs[2][16][136];   // [k][n]

    const int t  = threadIdx.x;
    const int n0 = blockIdx.x * 128, m0 = blockIdx.y * 128;

    const int lane = t & 31, w = t >> 5;
    const int wm = w & 1, wn = w >> 1;
    const int gid = lane >> 2, tig = lane & 3;
    const int mw = wm * 64, nw = wn * 32;

    const int amr = t >> 1;
    const int akc = (t & 1) * 8;
    const int bkr = t >> 4;
    const int bnc = (t & 15) * 8;

    float acc[4][4][4] = {};
    float4 pa0, pa1, pb0, pb1;

    {
        const float* Asrc = A;
        int kk0 = 0;
        if (MODE == 3 && 0 >= KA) { Asrc = A2; kk0 = -KA; }
        pa0 = *(const float4*)(Asrc + (size_t)(m0 + amr) * lda + kk0 + akc);
        pa1 = *(const float4*)(Asrc + (size_t)(m0 + amr) * lda + kk0 + akc + 4);
        pb0 = *(const float4*)(W + (size_t)bkr * N + n0 + bnc);
        pb1 = *(const float4*)(W + (size_t)bkr * N + n0 + bnc + 4);
    }
    {
        float av[8] = {pa0.x, pa0.y, pa0.z, pa0.w, pa1.x, pa1.y, pa1.z, pa1.w};
#pragma unroll
        for (int j = 0; j < 8; j++) As[0][akc + j][amr] = cvt_tf32(av[j]);
        float4 c0, c1;
        c0.x = cvt_tf32(pb0.x); c0.y = cvt_tf32(pb0.y);
        c0.z = cvt_tf32(pb0.z); c0.w = cvt_tf32(pb0.w);
        c1.x = cvt_tf32(pb1.x); c1.y = cvt_tf32(pb1.y);
        c1.z = cvt_tf32(pb1.z); c1.w = cvt_tf32(pb1.w);
        *(float4*)&Bs[0][bkr][bnc]     = c0;
        *(float4*)&Bs[0][bkr][bnc + 4] = c1;
    }
    __syncthreads();

    int buf = 0;
    for (int k0 = 0; k0 < K; k0 += 16) {
        const int kn = k0 + 16;
        const bool has_next = kn < K;
        if (has_next) {
            const float* Asrc = A;
            int kk0 = kn;
            if (MODE == 3 && kn >= KA) { Asrc = A2; kk0 = kn - KA; }
            pa0 = *(const float4*)(Asrc + (size_t)(m0 + amr) * lda + kk0 + akc);
            pa1 = *(const float4*)(Asrc + (size_t)(m0 + amr) * lda + kk0 + akc + 4);
            pb0 = *(const float4*)(W + (size_t)(kn + bkr) * N + n0 + bnc);
            pb1 = *(const float4*)(W + (size_t)(kn + bkr) * N + n0 + bnc + 4);
        }

#pragma unroll
        for (int kk = 0; kk < 16; kk += 8) {
            uint32_t af[4][4], bf[4][2];
#pragma unroll
            for (int mt = 0; mt < 4; mt++) {
                const int m = mw + mt * 16 + gid;
                af[mt][0] = __float_as_uint(As[buf][kk + tig][m]);
                af[mt][1] = __float_as_uint(As[buf][kk + tig][m + 8]);
                af[mt][2] = __float_as_uint(As[buf][kk + tig + 4][m]);
                af[mt][3] = __float_as_uint(As[buf][kk + tig + 4][m + 8]);
            }
#pragma unroll
            for (int nt = 0; nt < 4; nt++) {
                const int n = nw + nt * 8 + gid;
                bf[nt][0] = __float_as_uint(Bs[buf][kk + tig][n]);
                bf[nt][1] = __float_as_uint(Bs[buf][kk + tig + 4][n]);
            }
#pragma unroll
            for (int mt = 0; mt < 4; mt++)
#pragma unroll
                for (int nt = 0; nt < 4; nt++)
                    mma_tf32(acc[mt][nt], af[mt], bf[nt]);
        }

        if (has_next) {
            const int nb = buf ^ 1;
            float av[8] = {pa0.x, pa0.y, pa0.z, pa0.w, pa1.x, pa1.y, pa1.z, pa1.w};
#pragma unroll
            for (int j = 0; j < 8; j++) As[nb][akc + j][amr] = cvt_tf32(av[j]);
            float4 c0, c1;
            c0.x = cvt_tf32(pb0.x); c0.y = cvt_tf32(pb0.y);
            c0.z = cvt_tf32(pb0.z); c0.w = cvt_tf32(pb0.w);
            c1.x = cvt_tf32(pb1.x); c1.y = cvt_tf32(pb1.y);
            c1.z = cvt_tf32(pb1.z); c1.w = cvt_tf32(pb1.w);
            *(float4*)&Bs[nb][bkr][bnc]     = c0;
            *(float4*)&Bs[nb][bkr][bnc + 4] = c1;
        }
        __syncthreads();
        buf ^= 1;
    }

#pragma unroll
    for (int mt = 0; mt < 4; mt++) {
#pragma unroll
        for (int half = 0; half < 2; half++) {
            const int row = m0 + mw + mt * 16 + gid + half * 8;
#pragma unroll
            for (int nt = 0; nt < 4; nt++) {
                const int col = n0 + nw + nt * 8 + tig * 2;
                float v0 = acc[mt][nt][half * 2 + 0] + bias[col];
                float v1 = acc[mt][nt][half * 2 + 1] + bias[col + 1];
                if (MODE == 1) {
                    const size_t pr = (size_t)(row & (Ss - 1)) * N + col;
                    v0 += p1[pr]; v1 += p1[pr + 1];
                }
                if (MODE == 2) { v0 = fmaxf(v0, 0.f); v1 = fmaxf(v1, 0.f); }
                if (MODE == 3) {
                    const size_t pr = (size_t)row * N + col;
                    float g0 = tanhf(fmaxf(v0, 0.f));
                    float g1 = tanhf(fmaxf(v1, 0.f));
                    v0 = g0 * p1[pr] + (1.f - g0) * p2[pr];
                    v1 = g1 * p1[pr + 1] + (1.f - g1) * p2[pr + 1];
                }
                float2 o2; o2.x = v0; o2.y = v1;
                *(float2*)(C + (size_t)row * N + col) = o2;
            }
        }
    }
}

// ---------------- global attention: TF32 tensor-core flash -----------------
// Q-tile 128, K-tile 64, HD=64. 8 warps x 16 q-rows. All mma m16n8k8 tf32.
// smem (floats): Qs[128][68], Ps[128][68], Ks[64][68], Vs[64][72]
constexpr int FQ_OFF = 0;
constexpr int FP_OFF = 128 * 68;
constexpr int FK_OFF = 2 * 128 * 68;
constexpr int FV_OFF = FK_OFF + 64 * 68;
constexpr int FL_SMEM_FLOATS = FV_OFF + 64 * 72;
constexpr int FL_SMEM_BYTES  = FL_SMEM_FLOATS * 4;   // 105,472 B

__global__ void __launch_bounds__(256) flash_tc_k(
    const float* __restrict__ Q, const float* __restrict__ K,
    const float* __restrict__ V, float* __restrict__ O)
{
    extern __shared__ float sm[];
    float* Qs = sm + FQ_OFF;
    float* Ps = sm + FP_OFF;
    float* Ks = sm + FK_OFF;
    float* Vs = sm + FV_OFF;

    const int qt = blockIdx.x, h = blockIdx.y, b = blockIdx.z;
    const int t  = threadIdx.x;
    const int lane = t & 31, w = t >> 5;
    const int gid = lane >> 2, tig = lane & 3;
    const int q0 = w * 16;                       // warp's q-row base in tile

    // ---- load Q tile (pre-scaled, tf32) ----
    {
        const int r  = t >> 1;
        const int c0 = (t & 1) * 32;
        const float* src = Q + ((size_t)(b * Ss + qt * 128 + r)) * Dd + h * HD + c0;
#pragma unroll
        for (int i = 0; i < 8; i++) {
            float4 v = *(const float4*)(src + i * 4);
            Qs[r * 68 + c0 + i * 4 + 0] = cvt_tf32(v.x * SCALE);
            Qs[r * 68 + c0 + i * 4 + 1] = cvt_tf32(v.y * SCALE);
            Qs[r * 68 + c0 + i * 4 + 2] = cvt_tf32(v.z * SCALE);
            Qs[r * 68 + c0 + i * 4 + 3] = cvt_tf32(v.w * SCALE);
        }
    }

    float o_acc[8][4] = {};          // O fragments: 8 n-tiles over 64 dims
    float m0 = -INFINITY, m1 = -INFINITY, l0 = 0.f, l1 = 0.f;

    const int rowA0 = (q0 + gid) * 68;        // this thread's frag rows in Qs/Ps
    const int rowA1 = (q0 + gid + 8) * 68;

    for (int k0 = 0; k0 < Ss; k0 += 64) {
        __syncthreads();   // prior PV reads of Ks/Vs complete

        // ---- load K/V tile (tf32) ----
        {
            const int r  = t >> 2;
            const int c0 = (t & 3) * 16;
            const float* ks = K + ((size_t)(b * Ss + k0 + r)) * Dd + h * HD + c0;
            const float* vs = V + ((size_t)(b * Ss + k0 + r)) * Dd + h * HD + c0;
#pragma unroll
            for (int i = 0; i < 4; i++) {
                float4 kv = *(const float4*)(ks + i * 4);
                Ks[r * 68 + c0 + i * 4 + 0] = cvt_tf32(kv.x);
                Ks[r * 68 + c0 + i * 4 + 1] = cvt_tf32(kv.y);
                Ks[r * 68 + c0 + i * 4 + 2] = cvt_tf32(kv.z);
                Ks[r * 68 + c0 + i * 4 + 3] = cvt_tf32(kv.w);
                float4 vv = *(const float4*)(vs + i * 4);
                Vs[r * 72 + c0 + i * 4 + 0] = cvt_tf32(vv.x);
                Vs[r * 72 + c0 + i * 4 + 1] = cvt_tf32(vv.y);
                Vs[r * 72 + c0 + i * 4 + 2] = cvt_tf32(vv.z);
                Vs[r * 72 + c0 + i * 4 + 3] = cvt_tf32(vv.w);
            }
        }
        __syncthreads();

        // ---- S = Q K^T : sreg[nt][4], nt over 8 key-groups ----
        float sreg[8][4] = {};
#pragma unroll
        for (int kk = 0; kk < 8; kk++) {      // k-step over dims (8 per step)
            uint32_t a[4];
            a[0] = __float_as_uint(Qs[rowA0 + kk * 8 + tig]);
            a[1] = __float_as_uint(Qs[rowA1 + kk * 8 + tig]);
            a[2] = __float_as_uint(Qs[rowA0 + kk * 8 + tig + 4]);
            a[3] = __float_as_uint(Qs[rowA1 + kk * 8 + tig + 4]);
#pragma unroll
            for (int nt = 0; nt < 8; nt++) {
                uint32_t bf[2];
                bf[0] = __float_as_uint(Ks[(nt * 8 + gid) * 68 + kk * 8 + tig]);
                bf[1] = __float_as_uint(Ks[(nt * 8 + gid) * 68 + kk * 8 + tig + 4]);
                mma_tf32(sreg[nt], a, bf);
            }
        }

        // ---- online softmax (rows gid, gid+8; reduce over 4 tig lanes) ----
        float mt0 = -INFINITY, mt1 = -INFINITY;
#pragma unroll
        for (int nt = 0; nt < 8; nt++) {
            mt0 = fmaxf(mt0, fmaxf(sreg[nt][0], sreg[nt][1]));
            mt1 = fmaxf(mt1, fmaxf(sreg[nt][2], sreg[nt][3]));
        }
        mt0 = fmaxf(mt0, __shfl_xor_sync(0xffffffffu, mt0, 1));
        mt0 = fmaxf(mt0, __shfl_xor_sync(0xffffffffu, mt0, 2));
        mt1 = fmaxf(mt1, __shfl_xor_sync(0xffffffffu, mt1, 1));
        mt1 = fmaxf(mt1, __shfl_xor_sync(0xffffffffu, mt1, 2));

        const float mn0 = fmaxf(m0, mt0), mn1 = fmaxf(m1, mt1);
        const float al0 = __expf(m0 - mn0), al1 = __expf(m1 - mn1);
        m0 = mn0; m1 = mn1;

        float ls0 = 0.f, ls1 = 0.f;
#pragma unroll
        for (int nt = 0; nt < 8; nt++) {
            const float p00 = __expf(sreg[nt][0] - mn0);
            const float p01 = __expf(sreg[nt][1] - mn0);
            const float p10 = __expf(sreg[nt][2] - mn1);
            const float p11 = __expf(sreg[nt][3] - mn1);
            ls0 += p00 + p01;
            ls1 += p10 + p11;
            float2 w0; w0.x = cvt_tf32(p00); w0.y = cvt_tf32(p01);
            float2 w1; w1.x = cvt_tf32(p10); w1.y = cvt_tf32(p11);
            *(float2*)&Ps[rowA0 + nt * 8 + 2 * tig] = w0;
            *(float2*)&Ps[rowA1 + nt * 8 + 2 * tig] = w1;
        }
        ls0 += __shfl_xor_sync(0xffffffffu, ls0, 1);
        ls0 += __shfl_xor_sync(0xffffffffu, ls0, 2);
        ls1 += __shfl_xor_sync(0xffffffffu, ls1, 1);
        ls1 += __shfl_xor_sync(0xffffffffu, ls1, 2);
        l0 = l0 * al0 + ls0;
        l1 = l1 * al1 + ls1;
#pragma unroll
        for (int nt = 0; nt < 8; nt++) {
            o_acc[nt][0] *= al0; o_acc[nt][1] *= al0;
            o_acc[nt][2] *= al1; o_acc[nt][3] *= al1;
        }
        __syncwarp();   // Ps visible within warp (PV is warp-local)

        // ---- O += P V ----
#pragma unroll
        for (int kk = 0; kk < 8; kk++) {      // k-step over keys
            uint32_t a[4];
            a[0] = __float_as_uint(Ps[rowA0 + kk * 8 + tig]);
            a[1] = __float_as_uint(Ps[rowA1 + kk * 8 + tig]);
            a[2] = __float_as_uint(Ps[rowA0 + kk * 8 + tig + 4]);
            a[3] = __float_as_uint(Ps[rowA1 + kk * 8 + tig + 4]);
#pragma unroll
            for (int nt = 0; nt < 8; nt++) {  // n over 64 dims
                uint32_t bf[2];
                bf[0] = __float_as_uint(Vs[(kk * 8 + tig) * 72 + nt * 8 + gid]);
                bf[1] = __float_as_uint(Vs[(kk * 8 + tig + 4) * 72 + nt * 8 + gid]);
                mma_tf32(o_acc[nt], a, bf);
            }
        }
    }

    // ---- epilogue ----
    const float inv0 = 1.f / l0, inv1 = 1.f / l1;
    float* orow0 = O + ((size_t)(b * Ss + qt * 128 + q0 + gid)) * Dd + h * HD;
    float* orow1 = O + ((size_t)(b * Ss + qt * 128 + q0 + gid + 8)) * Dd + h * HD;
#pragma unroll
    for (int nt = 0; nt < 8; nt++) {
        float2 w0; w0.x = o_acc[nt][0] * inv0; w0.y = o_acc[nt][1] * inv0;
        float2 w1; w1.x = o_acc[nt][2] * inv1; w1.y = o_acc[nt][3] * inv1;
        *(float2*)(orow0 + nt * 8 + 2 * tig) = w0;
        *(float2*)(orow1 + nt * 8 + 2 * tig) = w1;
    }
}

// ---------------- local banded attention: warp per (b,h,q) ----------------
__global__ void __launch_bounds__(128) local_attn_k(
    const float* __restrict__ Q, const float* __restrict__ K,
    const float* __restrict__ V, float* __restrict__ O)
{
    const int wid = threadIdx.x >> 5, lane = threadIdx.x & 31;
    const int gw = blockIdx.x * 4 + wid;
    const int q = gw & (Ss - 1);
    const int bh = gw / Ss;
    const int h = bh & (Hh - 1);
    const int b = bh / Hh;

    __shared__ float sc[4][80];

    const float* qp = Q + ((size_t)(b * Ss + q)) * Dd + h * HD;
    const float q0 = qp[lane] * SCALE;
    const float q1 = qp[lane + 32] * SCALE;

    const int jlo = max(0, q - 32), jhi = min(Ss - 1, q + 32);
    const int n = jhi - jlo + 1;

    float m = -INFINITY;
    for (int j = jlo; j <= jhi; j++) {
        const float* kp = K + ((size_t)(b * Ss + j)) * Dd + h * HD;
        float s = q0 * kp[lane] + q1 * kp[lane + 32];
#pragma unroll
        for (int o = 16; o; o >>= 1) s += __shfl_xor_sync(0xffffffffu, s, o);
        if (!lane) sc[wid][j - jlo] = s;
        m = fmaxf(m, s);
    }
    __syncwarp();

    float l = 0.f;
    for (int idx = lane; idx < n; idx += 32) {
        float p = __expf(sc[wid][idx] - m);
        sc[wid][idx] = p;
        l += p;
    }
#pragma unroll
    for (int o = 16; o; o >>= 1) l += __shfl_xor_sync(0xffffffffu, l, o);
    __syncwarp();

    float a0 = 0.f, a1 = 0.f;
    for (int j = jlo; j <= jhi; j++) {
        const float p = sc[wid][j - jlo];
        const float* vp = V + ((size_t)(b * Ss + j)) * Dd + h * HD;
        a0 += p * vp[lane];
        a1 += p * vp[lane + 32];
    }
    const float inv = 1.f / l;
    float* op = O + ((size_t)(b * Ss + q)) * Dd + h * HD;
    op[lane] = a0 * inv;
    op[lane + 32] = a1 * inv;
}

// ---------------- LayerNorm kernels ----------------
__global__ void __launch_bounds__(128) ln_add_k(
    const float* __restrict__ A, const float* __restrict__ R,
    const float* __restrict__ g, const float* __restrict__ be,
    float* __restrict__ O)
{
    const int row = blockIdx.x, t = threadIdx.x;
    const size_t base = (size_t)row * Dd + t * 4;
    float4 a = *(const float4*)(A + base);
    float4 r = *(const float4*)(R + base);
    float x[4] = {a.x + r.x, a.y + r.y, a.z + r.z, a.w + r.w};

    float s = x[0] + x[1] + x[2] + x[3];
    float ss = x[0]*x[0] + x[1]*x[1] + x[2]*x[2] + x[3]*x[3];
    __shared__ float sh1[4], sh2[4];
#pragma unroll
    for (int o = 16; o; o >>= 1) {
        s  += __shfl_xor_sync(0xffffffffu, s, o);
        ss += __shfl_xor_sync(0xffffffffu, ss, o);
    }
    if (!(t & 31)) { sh1[t >> 5] = s; sh2[t >> 5] = ss; }
    __syncthreads();
    s  = sh1[0] + sh1[1] + sh1[2] + sh1[3];
    ss = sh2[0] + sh2[1] + sh2[2] + sh2[3];

    const float mean = s * (1.f / Dd);
    const float var = ss * (1.f / Dd) - mean * mean;
    const float rs = rsqrtf(var + 1e-5f);
    float4 gg = *(const float4*)(g + t * 4);
    float4 bb = *(const float4*)(be + t * 4);
    float4 o4;
    o4.x = (x[0] - mean) * rs * gg.x + bb.x;
    o4.y = (x[1] - mean) * rs * gg.y + bb.y;
    o4.z = (x[2] - mean) * rs * gg.z + bb.z;
    o4.w = (x[3] - mean) * rs * gg.w + bb.w;
    *(float4*)(O + base) = o4;
}

__global__ void __launch_bounds__(128) ln_add_ln_k(
    const float* __restrict__ A, const float* __restrict__ R,
    const float* __restrict__ g2, const float* __restrict__ b2,
    const float* __restrict__ g3, const float* __restrict__ b3,
    float* __restrict__ O)
{
    const int row = blockIdx.x, t = threadIdx.x;
    const size_t base = (size_t)row * Dd + t * 4;
    float4 a = *(const float4*)(A + base);
    float4 r = *(const float4*)(R + base);
    float x[4] = {a.x + r.x, a.y + r.y, a.z + r.z, a.w + r.w};

    __shared__ float sh1[4], sh2[4];
    float s = x[0] + x[1] + x[2] + x[3];
    float ss = x[0]*x[0] + x[1]*x[1] + x[2]*x[2] + x[3]*x[3];
#pragma unroll
    for (int o = 16; o; o >>= 1) {
        s  += __shfl_xor_sync(0xffffffffu, s, o);
        ss += __shfl_xor_sync(0xffffffffu, ss, o);
    }
    if (!(t & 31)) { sh1[t >> 5] = s; sh2[t >> 5] = ss; }
    __syncthreads();
    s  = sh1[0] + sh1[1] + sh1[2] + sh1[3];
    ss = sh2[0] + sh2[1] + sh2[2] + sh2[3];
    float mean = s * (1.f / Dd);
    float var = ss * (1.f / Dd) - mean * mean;
    float rs = rsqrtf(var + 1e-5f);

    float4 gg = *(const float4*)(g2 + t * 4);
    float4 bb = *(const float4*)(b2 + t * 4);
    float y[4];
    y[0] = (x[0] - mean) * rs * gg.x + bb.x;
    y[1] = (x[1] - mean) * rs * gg.y + bb.y;
    y[2] = (x[2] - mean) * rs * gg.z + bb.z;
    y[3] = (x[3] - mean) * rs * gg.w + bb.w;

    __syncthreads();
    s  = y[0] + y[1] + y[2] + y[3];
    ss = y[0]*y[0] + y[1]*y[1] + y[2]*y[2] + y[3]*y[3];
#pragma unroll
    for (int o = 16; o; o >>= 1) {
        s  += __shfl_xor_sync(0xffffffffu, s, o);
        ss += __shfl_xor_sync(0xffffffffu, ss, o);
    }
    if (!(t & 31)) { sh1[t >> 5] = s; sh2[t >> 5] = ss; }
    __syncthreads();
    s  = sh1[0] + sh1[1] + sh1[2] + sh1[3];
    ss = sh2[0] + sh2[1] + sh2[2] + sh2[3];
    mean = s * (1.f / Dd);
    var = ss * (1.f / Dd) - mean * mean;
    rs = rsqrtf(var + 1e-5f);

    float4 g3v = *(const float4*)(g3 + t * 4);
    float4 b3v = *(const float4*)(b3 + t * 4);
    float4 o4;
    o4.x = (y[0] - mean) * rs * g3v.x + b3v.x;
    o4.y = (y[1] - mean) * rs * g3v.y + b3v.y;
    o4.z = (y[2] - mean) * rs * g3v.z + b3v.z;
    o4.w = (y[3] - mean) * rs * g3v.w + b3v.w;
    *(float4*)(O + base) = o4;
}

// ---------------- mean pool over S (deterministic 2-stage) ----------------
__global__ void __launch_bounds__(128) colmean_part_k(const float* __restrict__ X,
                                                      float* __restrict__ PP)
{
    const int b = blockIdx.x >> 2;
    const int d = (blockIdx.x & 3) * 128 + threadIdx.x;
    const int sc = blockIdx.y;
    float s = 0.f;
    for (int j = sc * 128; j < sc * 128 + 128; j++)
        s += X[((size_t)(b * Ss + j)) * Dd + d];
    PP[((size_t)sc * Bb + b) * Dd + d] = s;
}

__global__ void __launch_bounds__(128) colmean_fin_k(const float* __restrict__ PP,
                                                     float* __restrict__ P)
{
    const int idx = blockIdx.x * 128 + threadIdx.x;
    const int b = idx / Dd, d = idx % Dd;
    float s = 0.f;
#pragma unroll
    for (int c = 0; c < 16; c++) s += PP[((size_t)c * Bb + b) * Dd + d];
    P[idx] = s * (1.f / Ss);
}

// ---------------- final tiny GEMM ----------------
__global__ void __launch_bounds__(128) final_k(const float* __restrict__ P,
                                               const float* __restrict__ Wt,
                                               const float* __restrict__ bias,
                                               float* __restrict__ out)
{
    const int b = blockIdx.x, o = threadIdx.x;
    float s = bias[o];
    for (int d = 0; d < Dd; d++) s += P[b * Dd + d] * Wt[d * DOUT + o];
    out[b * DOUT + o] = s;
}

// ---------------- launch ----------------
extern "C" void kernel_launch(void* const* d_in, const int* in_sizes, int n_in,
                              void* d_out, int out_size)
{
    const float* x      = (const float*)d_in[0];
    const float* pos    = (const float*)d_in[1];
    const float* win_w  = (const float*)d_in[2];
    const float* win_b  = (const float*)d_in[3];
    const float* l_wqkv = (const float*)d_in[4];
    const float* l_bqkv = (const float*)d_in[5];
    const float* l_wo   = (const float*)d_in[6];
    const float* l_bo   = (const float*)d_in[7];
    const float* g_wqkv = (const float*)d_in[8];
    const float* g_bqkv = (const float*)d_in[9];
    const float* g_wo   = (const float*)d_in[10];
    const float* g_bo   = (const float*)d_in[11];
    const float* gate_w = (const float*)d_in[12];
    const float* gate_b = (const float*)d_in[13];
    const float* ffn_w1 = (const float*)d_in[14];
    const float* ffn_b1 = (const float*)d_in[15];
    const float* ffn_w2 = (const float*)d_in[16];
    const float* ffn_b2 = (const float*)d_in[17];
    const float* n1_g   = (const float*)d_in[18];
    const float* n1_b   = (const float*)d_in[19];
    const float* n2_g   = (const float*)d_in[20];
    const float* n2_b   = (const float*)d_in[21];
    const float* n3_g   = (const float*)d_in[22];
    const float* n3_b   = (const float*)d_in[23];
    const float* out_w  = (const float*)d_in[24];
    const float* out_b  = (const float*)d_in[25];

    float* sp = nullptr;
    cudaGetSymbolAddress((void**)&sp, g_scratch);
    float* bH   = sp + O_H;
    float* bQ   = sp + O_Q;
    float* bK   = sp + O_K;
    float* bV   = sp + O_V;
    float* bAO  = sp + O_AO;
    float* bLOC = sp + O_LOC;
    float* bGLO = sp + O_GLO;
    float* bFUS = sp + O_FUS;
    float* bH1  = sp + O_H1;
    float* bFFN = sp + O_FFN;
    float* bH3  = sp + O_H3;
    float* bT1  = sp + O_T1;
    float* bPP  = sp + O_PP;
    float* bP   = sp + O_P;

    static bool attr_set = false;
    if (!attr_set) {
        cudaFuncSetAttribute(flash_tc_k, cudaFuncAttributeMaxDynamicSharedMemorySize,
                             FL_SMEM_BYTES);
        attr_set = true;
    }

    const dim3 blk(256);
    const dim3 gD(Dd / 128, BS / 128);        // N=512 GEMMs
    const dim3 gD2(2 * Dd / 128, BS / 128);   // N=1024 GEMM

    // 1. h = x @ win_w + win_b + pos
    gemm_tc_k<1><<<gD, blk>>>(x, nullptr, DIN, 0, win_w, win_b, pos, nullptr,
                              bH, BS, Dd, DIN);

    // 2. local QKV
    float* qkv[3] = {bQ, bK, bV};
    for (int i = 0; i < 3; i++)
        gemm_tc_k<0><<<gD, blk>>>(bH, nullptr, Dd, 0, l_wqkv + (size_t)i * Dd * Dd,
                                  l_bqkv + i * Dd, nullptr, nullptr, qkv[i], BS, Dd, Dd);

    // 3. local banded attention
    local_attn_k<<<(Bb * Hh * Ss) / 4, 128>>>(bQ, bK, bV, bAO);

    // 4. local_out = attn_o @ l_wo + l_bo
    gemm_tc_k<0><<<gD, blk>>>(bAO, nullptr, Dd, 0, l_wo, l_bo, nullptr, nullptr,
                              bLOC, BS, Dd, Dd);

    // 5. global QKV
    for (int i = 0; i < 3; i++)
        gemm_tc_k<0><<<gD, blk>>>(bH, nullptr, Dd, 0, g_wqkv + (size_t)i * Dd * Dd,
                                  g_bqkv + i * Dd, nullptr, nullptr, qkv[i], BS, Dd, Dd);

    // 6. global flash attention (TF32 tensor cores)
    flash_tc_k<<<dim3(Ss / 128, Hh, Bb), 256, FL_SMEM_BYTES>>>(bQ, bK, bV, bAO);

    // 7. global_out
    gemm_tc_k<0><<<gD, blk>>>(bAO, nullptr, Dd, 0, g_wo, g_bo, nullptr, nullptr,
                              bGLO, BS, Dd, Dd);

    // 8. gate GEMM fused with blend
    gemm_tc_k<3><<<gD, blk>>>(bLOC, bGLO, Dd, Dd, gate_w, gate_b, bLOC, bGLO,
                              bFUS, BS, Dd, 2 * Dd);

    // 9. h1 = LN(h + fused)
    ln_add_k<<<BS, 128>>>(bH, bFUS, n1_g, n1_b, bH1);

    // 10. FFN
    gemm_tc_k<2><<<gD2, blk>>>(bH1, nullptr, Dd, 0, ffn_w1, ffn_b1, nullptr, nullptr,
                               bT1, BS, 2 * Dd, Dd);
    gemm_tc_k<0><<<gD, blk>>>(bT1, nullptr, 2 * Dd, 0, ffn_w2, ffn_b2, nullptr, nullptr,
                              bFFN, BS, Dd, 2 * Dd);

    // 11. h3 = LN(LN(h1 + ffn))
    ln_add_ln_k<<<BS, 128>>>(bH1, bFFN, n2_g, n2_b, n3_g, n3_b, bH3);

    // 12. mean-pool over S, then final projection
    colmean_part_k<<<dim3(Bb * 4, 16), 128>>>(bH3, bPP);
    colmean_fin_k<<<(Bb * Dd) / 128, 128>>>(bPP, bP);
    final_k<<<Bb, DOUT>>>(bP, out_w, out_b, (float*)d_out);

    (void)in_sizes; (void)n_in; (void)out_size;
}

// round 5
// speedup vs baseline: 3.6939x; 1.1925x over previous
#include <cuda_runtime.h>
#include <math.h>
#include <stdint.h>

// ---------------- problem constants (hardcoded) ----------------
constexpr int   Bb   = 4;
constexpr int   Ss   = 2048;
constexpr int   DIN  = 256;
constexpr int   Dd   = 512;
constexpr int   Hh   = 8;
constexpr int   DOUT = 128;
constexpr int   HD   = 64;       // Dd / Hh
constexpr int   BS   = Bb * Ss;  // 8192 rows
constexpr float SCALE = 0.125f;  // 1/sqrt(64)

// ---------------- scratch (static device memory; no allocs) ----------------
constexpr size_t NBD  = (size_t)BS * Dd;
constexpr size_t O_H   = 0;
constexpr size_t O_QL  = 1 * NBD;   // QL,KL,VL,QG,KG,VG consecutive
constexpr size_t O_KL  = 2 * NBD;
constexpr size_t O_VL  = 3 * NBD;
constexpr size_t O_QG  = 4 * NBD;
constexpr size_t O_KG  = 5 * NBD;
constexpr size_t O_VG  = 6 * NBD;
constexpr size_t O_AOL = 7 * NBD;
constexpr size_t O_AOG = 8 * NBD;
constexpr size_t O_LOC = 9 * NBD;   // LOC,GLO consecutive
constexpr size_t O_GLO = 10 * NBD;
constexpr size_t O_FUS = 11 * NBD;
constexpr size_t O_H1  = 12 * NBD;
constexpr size_t O_FFN = 13 * NBD;
constexpr size_t O_H3  = 14 * NBD;
constexpr size_t O_T1  = 15 * NBD;  // 2*NBD wide
constexpr size_t O_PP  = 17 * NBD;
constexpr size_t O_P   = 17 * NBD + (size_t)16 * Bb * Dd;
constexpr size_t SCRATCH_FLOATS = O_P + (size_t)Bb * Dd;

__device__ float g_scratch[SCRATCH_FLOATS];

// ---------------- helpers: tf32 convert + mma + ldmatrix ----------------
__device__ __forceinline__ float cvt_tf32(float x) {
    uint32_t u;
    asm("cvt.rna.tf32.f32 %0, %1;" : "=r"(u) : "f"(x));
    return __uint_as_float(u);
}

__device__ __forceinline__ void mma_tf32(float c[4], const uint32_t a[4],
                                         const uint32_t b[2]) {
    asm volatile(
        "mma.sync.aligned.m16n8k8.row.col.f32.tf32.tf32.f32 "
        "{%0,%1,%2,%3},{%4,%5,%6,%7},{%8,%9},{%0,%1,%2,%3};\n"
        : "+f"(c[0]), "+f"(c[1]), "+f"(c[2]), "+f"(c[3])
        : "r"(a[0]), "r"(a[1]), "r"(a[2]), "r"(a[3]), "r"(b[0]), "r"(b[1]));
}

__device__ __forceinline__ void ldsm_x4(uint32_t r[4], uint32_t saddr) {
    asm volatile("ldmatrix.sync.aligned.m8n8.x4.shared.b16 {%0,%1,%2,%3}, [%4];"
                 : "=r"(r[0]), "=r"(r[1]), "=r"(r[2]), "=r"(r[3]) : "r"(saddr));
}

__device__ __forceinline__ uint32_t smem_u32(const void* p) {
    uint32_t a;
    asm("{ .reg .u64 t; cvta.to.shared.u64 t, %1; cvt.u32.u64 %0, t; }"
        : "=r"(a) : "l"(p));
    return a;
}

// ---------------- TF32 tensor-core GEMM, 128x128 tile, fused epilogues -----
// MODE 0: +bias
// MODE 1: +bias + pos[(row%S)*N + col]
// MODE 2: relu(+bias)
// MODE 3: A=concat(A,A2) on K (split KA); g=tanh(relu(acc+bias)); C=g*p1+(1-g)*p2
// MODE 4: 6-slice QKV: isl=bx>>2; W = isl<3? W+isl*D*D : p1+(isl-3)*D*D;
//         bias = isl<3? bias+isl*D : A2+(isl-3)*D; C += isl*NBD
// MODE 5: 2-slice Wo:  isl=bx>>2; A = isl? A2:A; W = isl? p1:W;
//         bias = isl? p2:bias; C += isl*NBD
// A-fragments via ldmatrix from As[m][RSA] (m-major).
constexpr int RSA = 20;

template <int MODE>
__global__ void __launch_bounds__(256) gemm_tc_k(
    const float* __restrict__ A, const float* __restrict__ A2, int lda, int KA,
    const float* __restrict__ W, const float* __restrict__ bias,
    const float* __restrict__ p1, const float* __restrict__ p2,
    float* __restrict__ C, int M, int N, int K)
{
    __shared__ float As[2][128][RSA];   // [m][k], k-tile 16 + pad
    __shared__ float Bs[2][16][136];    // [k][n]

    const int t  = threadIdx.x;
    const int m0 = blockIdx.y * 128;

    // ---- slice / column-base resolution ----
    const float* Asel = A;
    const float* Wsel = W;
    const float* bsel = bias;
    float* Csel = C;
    int n0;
    if (MODE == 4 || MODE == 5) {
        const int isl = blockIdx.x >> 2;
        n0 = (blockIdx.x & 3) * 128;
        if (MODE == 4) {
            Wsel = (isl < 3) ? W + (size_t)isl * Dd * Dd
                             : p1 + (size_t)(isl - 3) * Dd * Dd;
            bsel = (isl < 3) ? bias + isl * Dd : A2 + (isl - 3) * Dd;
        } else {
            Asel = isl ? A2 : A;
            Wsel = isl ? p1 : W;
            bsel = isl ? p2 : bias;
        }
        Csel = C + (size_t)isl * NBD;
    } else {
        n0 = blockIdx.x * 128;
    }

    const int lane = t & 31, w = t >> 5;
    const int wm = w & 1, wn = w >> 1;
    const int gid = lane >> 2, tig = lane & 3;
    const int mw = wm * 64, nw = wn * 32;

    const int amr = t >> 1;          // A loader: m row 0..127
    const int akc = (t & 1) * 8;     // A loader: k col 0 or 8
    const int bkr = t >> 4;          // B loader: k row 0..15
    const int bnc = (t & 15) * 8;    // B loader: n col 0..120

    // ldmatrix lane geometry for A-frags
    const int lm_row = (lane & 7) + (lane & 8);     // 0..15
    const int lm_kc  = (lane >> 2) & 4;             // 0 or 4
    const uint32_t aAddr0 = smem_u32(&As[0][mw + lm_row][lm_kc]);
    const uint32_t aAddr1 = smem_u32(&As[1][mw + lm_row][lm_kc]);

    float acc[4][4][4] = {};
    float4 pa0, pa1, pb0, pb1;

    // ---- prefetch tile 0 ----
    {
        const float* Asrc = Asel;
        int kk0 = 0;
        if (MODE == 3 && 0 >= KA) { Asrc = A2; kk0 = -KA; }
        pa0 = *(const float4*)(Asrc + (size_t)(m0 + amr) * lda + kk0 + akc);
        pa1 = *(const float4*)(Asrc + (size_t)(m0 + amr) * lda + kk0 + akc + 4);
        pb0 = *(const float4*)(Wsel + (size_t)bkr * N + n0 + bnc);
        pb1 = *(const float4*)(Wsel + (size_t)bkr * N + n0 + bnc + 4);
    }
    {
        float4 a0, a1;
        a0.x = cvt_tf32(pa0.x); a0.y = cvt_tf32(pa0.y);
        a0.z = cvt_tf32(pa0.z); a0.w = cvt_tf32(pa0.w);
        a1.x = cvt_tf32(pa1.x); a1.y = cvt_tf32(pa1.y);
        a1.z = cvt_tf32(pa1.z); a1.w = cvt_tf32(pa1.w);
        *(float4*)&As[0][amr][akc]     = a0;
        *(float4*)&As[0][amr][akc + 4] = a1;
        float4 c0, c1;
        c0.x = cvt_tf32(pb0.x); c0.y = cvt_tf32(pb0.y);
        c0.z = cvt_tf32(pb0.z); c0.w = cvt_tf32(pb0.w);
        c1.x = cvt_tf32(pb1.x); c1.y = cvt_tf32(pb1.y);
        c1.z = cvt_tf32(pb1.z); c1.w = cvt_tf32(pb1.w);
        *(float4*)&Bs[0][bkr][bnc]     = c0;
        *(float4*)&Bs[0][bkr][bnc + 4] = c1;
    }
    __syncthreads();

    int buf = 0;
    for (int k0 = 0; k0 < K; k0 += 16) {
        const int kn = k0 + 16;
        const bool has_next = kn < K;
        if (has_next) {
            const float* Asrc = Asel;
            int kk0 = kn;
            if (MODE == 3 && kn >= KA) { Asrc = A2; kk0 = kn - KA; }
            pa0 = *(const float4*)(Asrc + (size_t)(m0 + amr) * lda + kk0 + akc);
            pa1 = *(const float4*)(Asrc + (size_t)(m0 + amr) * lda + kk0 + akc + 4);
            pb0 = *(const float4*)(Wsel + (size_t)(kn + bkr) * N + n0 + bnc);
            pb1 = *(const float4*)(Wsel + (size_t)(kn + bkr) * N + n0 + bnc + 4);
        }

        const uint32_t aAddr = buf ? aAddr1 : aAddr0;
#pragma unroll
        for (int kk = 0; kk < 16; kk += 8) {
            uint32_t af[4][4], bf[4][2];
#pragma unroll
            for (int mt = 0; mt < 4; mt++)
                ldsm_x4(af[mt], aAddr + (uint32_t)((mt * 16 * RSA + kk) * 4));
#pragma unroll
            for (int nt = 0; nt < 4; nt++) {
                const int n = nw + nt * 8 + gid;
                bf[nt][0] = __float_as_uint(Bs[buf][kk + tig][n]);
                bf[nt][1] = __float_as_uint(Bs[buf][kk + tig + 4][n]);
            }
#pragma unroll
            for (int mt = 0; mt < 4; mt++)
#pragma unroll
                for (int nt = 0; nt < 4; nt++)
                    mma_tf32(acc[mt][nt], af[mt], bf[nt]);
        }

        if (has_next) {
            const int nb = buf ^ 1;
            float4 a0, a1;
            a0.x = cvt_tf32(pa0.x); a0.y = cvt_tf32(pa0.y);
            a0.z = cvt_tf32(pa0.z); a0.w = cvt_tf32(pa0.w);
            a1.x = cvt_tf32(pa1.x); a1.y = cvt_tf32(pa1.y);
            a1.z = cvt_tf32(pa1.z); a1.w = cvt_tf32(pa1.w);
            *(float4*)&As[nb][amr][akc]     = a0;
            *(float4*)&As[nb][amr][akc + 4] = a1;
            float4 c0, c1;
            c0.x = cvt_tf32(pb0.x); c0.y = cvt_tf32(pb0.y);
            c0.z = cvt_tf32(pb0.z); c0.w = cvt_tf32(pb0.w);
            c1.x = cvt_tf32(pb1.x); c1.y = cvt_tf32(pb1.y);
            c1.z = cvt_tf32(pb1.z); c1.w = cvt_tf32(pb1.w);
            *(float4*)&Bs[nb][bkr][bnc]     = c0;
            *(float4*)&Bs[nb][bkr][bnc + 4] = c1;
        }
        __syncthreads();
        buf ^= 1;
    }

    // ---- epilogue ----
#pragma unroll
    for (int mt = 0; mt < 4; mt++) {
#pragma unroll
        for (int half = 0; half < 2; half++) {
            const int row = m0 + mw + mt * 16 + gid + half * 8;
#pragma unroll
            for (int nt = 0; nt < 4; nt++) {
                const int col = n0 + nw + nt * 8 + tig * 2;
                float v0 = acc[mt][nt][half * 2 + 0] + bsel[col];
                float v1 = acc[mt][nt][half * 2 + 1] + bsel[col + 1];
                if (MODE == 1) {
                    const size_t pr = (size_t)(row & (Ss - 1)) * N + col;
                    v0 += p1[pr]; v1 += p1[pr + 1];
                }
                if (MODE == 2) { v0 = fmaxf(v0, 0.f); v1 = fmaxf(v1, 0.f); }
                if (MODE == 3) {
                    const size_t pr = (size_t)row * N + col;
                    float g0 = tanhf(fmaxf(v0, 0.f));
                    float g1 = tanhf(fmaxf(v1, 0.f));
                    v0 = g0 * p1[pr] + (1.f - g0) * p2[pr];
                    v1 = g1 * p1[pr + 1] + (1.f - g1) * p2[pr + 1];
                }
                float2 o2; o2.x = v0; o2.y = v1;
                *(float2*)(Csel + (size_t)row * N + col) = o2;
            }
        }
    }
}

// ---------------- TF32 tensor-core flash attention ------------------------
// BANDED=0: full attention over S. BANDED=1: band |q-k|<=32 (4 k-tiles).
// Q-tile 128, K-tile 64, HD=64. 8 warps x 16 q-rows, mma m16n8k8.
constexpr int FQ_OFF = 0;
constexpr int FP_OFF = 128 * 68;
constexpr int FK_OFF = 2 * 128 * 68;
constexpr int FV_OFF = FK_OFF + 64 * 68;
constexpr int FL_SMEM_FLOATS = FV_OFF + 64 * 72;
constexpr int FL_SMEM_BYTES  = FL_SMEM_FLOATS * 4;   // 105,472 B

template <int BANDED>
__global__ void __launch_bounds__(256) flash_tc_k(
    const float* __restrict__ Q, const float* __restrict__ K,
    const float* __restrict__ V, float* __restrict__ O)
{
    extern __shared__ float sm[];
    float* Qs = sm + FQ_OFF;
    float* Ps = sm + FP_OFF;
    float* Ks = sm + FK_OFF;
    float* Vs = sm + FV_OFF;

    const int qt = blockIdx.x, h = blockIdx.y, b = blockIdx.z;
    const int t  = threadIdx.x;
    const int lane = t & 31, w = t >> 5;
    const int gid = lane >> 2, tig = lane & 3;
    const int q0 = w * 16;

    // ---- load Q tile (pre-scaled, tf32) ----
    {
        const int r  = t >> 1;
        const int c0 = (t & 1) * 32;
        const float* src = Q + ((size_t)(b * Ss + qt * 128 + r)) * Dd + h * HD + c0;
#pragma unroll
        for (int i = 0; i < 8; i++) {
            float4 v = *(const float4*)(src + i * 4);
            Qs[r * 68 + c0 + i * 4 + 0] = cvt_tf32(v.x * SCALE);
            Qs[r * 68 + c0 + i * 4 + 1] = cvt_tf32(v.y * SCALE);
            Qs[r * 68 + c0 + i * 4 + 2] = cvt_tf32(v.z * SCALE);
            Qs[r * 68 + c0 + i * 4 + 3] = cvt_tf32(v.w * SCALE);
        }
    }

    float o_acc[8][4] = {};
    float m0 = BANDED ? -1e30f : -INFINITY;
    float m1 = m0;
    float l0 = 0.f, l1 = 0.f;

    const int rowA0 = (q0 + gid) * 68;
    const int rowA1 = (q0 + gid + 8) * 68;
    const int qr0 = qt * 128 + q0 + gid;       // global q rows for masking
    const int qr1 = qr0 + 8;

    int k_begin = 0, k_end = Ss;
    if (BANDED) {
        k_begin = qt * 128 - 64; if (k_begin < 0) k_begin = 0;
        k_end   = qt * 128 + 192; if (k_end > Ss) k_end = Ss;
    }

    for (int k0 = k_begin; k0 < k_end; k0 += 64) {
        __syncthreads();

        // ---- load K/V tile (tf32) ----
        {
            const int r  = t >> 2;
            const int c0 = (t & 3) * 16;
            const float* ks = K + ((size_t)(b * Ss + k0 + r)) * Dd + h * HD + c0;
            const float* vs = V + ((size_t)(b * Ss + k0 + r)) * Dd + h * HD + c0;
#pragma unroll
            for (int i = 0; i < 4; i++) {
                float4 kv = *(const float4*)(ks + i * 4);
                Ks[r * 68 + c0 + i * 4 + 0] = cvt_tf32(kv.x);
                Ks[r * 68 + c0 + i * 4 + 1] = cvt_tf32(kv.y);
                Ks[r * 68 + c0 + i * 4 + 2] = cvt_tf32(kv.z);
                Ks[r * 68 + c0 + i * 4 + 3] = cvt_tf32(kv.w);
                float4 vv = *(const float4*)(vs + i * 4);
                Vs[r * 72 + c0 + i * 4 + 0] = cvt_tf32(vv.x);
                Vs[r * 72 + c0 + i * 4 + 1] = cvt_tf32(vv.y);
                Vs[r * 72 + c0 + i * 4 + 2] = cvt_tf32(vv.z);
                Vs[r * 72 + c0 + i * 4 + 3] = cvt_tf32(vv.w);
            }
        }
        __syncthreads();

        // ---- S = Q K^T ----
        float sreg[8][4] = {};
#pragma unroll
        for (int kk = 0; kk < 8; kk++) {
            uint32_t a[4];
            a[0] = __float_as_uint(Qs[rowA0 + kk * 8 + tig]);
            a[1] = __float_as_uint(Qs[rowA1 + kk * 8 + tig]);
            a[2] = __float_as_uint(Qs[rowA0 + kk * 8 + tig + 4]);
            a[3] = __float_as_uint(Qs[rowA1 + kk * 8 + tig + 4]);
#pragma unroll
            for (int nt = 0; nt < 8; nt++) {
                uint32_t bf[2];
                bf[0] = __float_as_uint(Ks[(nt * 8 + gid) * 68 + kk * 8 + tig]);
                bf[1] = __float_as_uint(Ks[(nt * 8 + gid) * 68 + kk * 8 + tig + 4]);
                mma_tf32(sreg[nt], a, bf);
            }
        }

        // ---- band mask ----
        if (BANDED) {
#pragma unroll
            for (int nt = 0; nt < 8; nt++) {
                const int kg = k0 + nt * 8 + 2 * tig;
                if (abs(qr0 - kg)       > 32) sreg[nt][0] = -1e30f;
                if (abs(qr0 - (kg + 1)) > 32) sreg[nt][1] = -1e30f;
                if (abs(qr1 - kg)       > 32) sreg[nt][2] = -1e30f;
                if (abs(qr1 - (kg + 1)) > 32) sreg[nt][3] = -1e30f;
            }
        }

        // ---- online softmax ----
        float mt0 = -1e30f, mt1 = -1e30f;
#pragma unroll
        for (int nt = 0; nt < 8; nt++) {
            mt0 = fmaxf(mt0, fmaxf(sreg[nt][0], sreg[nt][1]));
            mt1 = fmaxf(mt1, fmaxf(sreg[nt][2], sreg[nt][3]));
        }
        mt0 = fmaxf(mt0, __shfl_xor_sync(0xffffffffu, mt0, 1));
        mt0 = fmaxf(mt0, __shfl_xor_sync(0xffffffffu, mt0, 2));
        mt1 = fmaxf(mt1, __shfl_xor_sync(0xffffffffu, mt1, 1));
        mt1 = fmaxf(mt1, __shfl_xor_sync(0xffffffffu, mt1, 2));

        const float mn0 = fmaxf(m0, mt0), mn1 = fmaxf(m1, mt1);
        const float al0 = __expf(m0 - mn0), al1 = __expf(m1 - mn1);
        m0 = mn0; m1 = mn1;

        float ls0 = 0.f, ls1 = 0.f;
#pragma unroll
        for (int nt = 0; nt < 8; nt++) {
            float p00, p01, p10, p11;
            if (BANDED) {
                p00 = (sreg[nt][0] > -1e29f) ? __expf(sreg[nt][0] - mn0) : 0.f;
                p01 = (sreg[nt][1] > -1e29f) ? __expf(sreg[nt][1] - mn0) : 0.f;
                p10 = (sreg[nt][2] > -1e29f) ? __expf(sreg[nt][2] - mn1) : 0.f;
                p11 = (sreg[nt][3] > -1e29f) ? __expf(sreg[nt][3] - mn1) : 0.f;
            } else {
                p00 = __expf(sreg[nt][0] - mn0);
                p01 = __expf(sreg[nt][1] - mn0);
                p10 = __expf(sreg[nt][2] - mn1);
                p11 = __expf(sreg[nt][3] - mn1);
            }
            ls0 += p00 + p01;
            ls1 += p10 + p11;
            float2 w0; w0.x = cvt_tf32(p00); w0.y = cvt_tf32(p01);
            float2 w1; w1.x = cvt_tf32(p10); w1.y = cvt_tf32(p11);
            *(float2*)&Ps[rowA0 + nt * 8 + 2 * tig] = w0;
            *(float2*)&Ps[rowA1 + nt * 8 + 2 * tig] = w1;
        }
        ls0 += __shfl_xor_sync(0xffffffffu, ls0, 1);
        ls0 += __shfl_xor_sync(0xffffffffu, ls0, 2);
        ls1 += __shfl_xor_sync(0xffffffffu, ls1, 1);
        ls1 += __shfl_xor_sync(0xffffffffu, ls1, 2);
        l0 = l0 * al0 + ls0;
        l1 = l1 * al1 + ls1;
#pragma unroll
        for (int nt = 0; nt < 8; nt++) {
            o_acc[nt][0] *= al0; o_acc[nt][1] *= al0;
            o_acc[nt][2] *= al1; o_acc[nt][3] *= al1;
        }
        __syncwarp();

        // ---- O += P V ----
#pragma unroll
        for (int kk = 0; kk < 8; kk++) {
            uint32_t a[4];
            a[0] = __float_as_uint(Ps[rowA0 + kk * 8 + tig]);
            a[1] = __float_as_uint(Ps[rowA1 + kk * 8 + tig]);
            a[2] = __float_as_uint(Ps[rowA0 + kk * 8 + tig + 4]);
            a[3] = __float_as_uint(Ps[rowA1 + kk * 8 + tig + 4]);
#pragma unroll
            for (int nt = 0; nt < 8; nt++) {
                uint32_t bf[2];
                bf[0] = __float_as_uint(Vs[(kk * 8 + tig) * 72 + nt * 8 + gid]);
                bf[1] = __float_as_uint(Vs[(kk * 8 + tig + 4) * 72 + nt * 8 + gid]);
                mma_tf32(o_acc[nt], a, bf);
            }
        }
    }

    // ---- epilogue ----
    const float inv0 = 1.f / l0, inv1 = 1.f / l1;
    float* orow0 = O + ((size_t)(b * Ss + qt * 128 + q0 + gid)) * Dd + h * HD;
    float* orow1 = O + ((size_t)(b * Ss + qt * 128 + q0 + gid + 8)) * Dd + h * HD;
#pragma unroll
    for (int nt = 0; nt < 8; nt++) {
        float2 w0; w0.x = o_acc[nt][0] * inv0; w0.y = o_acc[nt][1] * inv0;
        float2 w1; w1.x = o_acc[nt][2] * inv1; w1.y = o_acc[nt][3] * inv1;
        *(float2*)(orow0 + nt * 8 + 2 * tig) = w0;
        *(float2*)(orow1 + nt * 8 + 2 * tig) = w1;
    }
}

// ---------------- LayerNorm kernels ----------------
__global__ void __launch_bounds__(128) ln_add_k(
    const float* __restrict__ A, const float* __restrict__ R,
    const float* __restrict__ g, const float* __restrict__ be,
    float* __restrict__ O)
{
    const int row = blockIdx.x, t = threadIdx.x;
    const size_t base = (size_t)row * Dd + t * 4;
    float4 a = *(const float4*)(A + base);
    float4 r = *(const float4*)(R + base);
    float x[4] = {a.x + r.x, a.y + r.y, a.z + r.z, a.w + r.w};

    float s = x[0] + x[1] + x[2] + x[3];
    float ss = x[0]*x[0] + x[1]*x[1] + x[2]*x[2] + x[3]*x[3];
    __shared__ float sh1[4], sh2[4];
#pragma unroll
    for (int o = 16; o; o >>= 1) {
        s  += __shfl_xor_sync(0xffffffffu, s, o);
        ss += __shfl_xor_sync(0xffffffffu, ss, o);
    }
    if (!(t & 31)) { sh1[t >> 5] = s; sh2[t >> 5] = ss; }
    __syncthreads();
    s  = sh1[0] + sh1[1] + sh1[2] + sh1[3];
    ss = sh2[0] + sh2[1] + sh2[2] + sh2[3];

    const float mean = s * (1.f / Dd);
    const float var = ss * (1.f / Dd) - mean * mean;
    const float rs = rsqrtf(var + 1e-5f);
    float4 gg = *(const float4*)(g + t * 4);
    float4 bb = *(const float4*)(be + t * 4);
    float4 o4;
    o4.x = (x[0] - mean) * rs * gg.x + bb.x;
    o4.y = (x[1] - mean) * rs * gg.y + bb.y;
    o4.z = (x[2] - mean) * rs * gg.z + bb.z;
    o4.w = (x[3] - mean) * rs * gg.w + bb.w;
    *(float4*)(O + base) = o4;
}

__global__ void __launch_bounds__(128) ln_add_ln_k(
    const float* __restrict__ A, const float* __restrict__ R,
    const float* __restrict__ g2, const float* __restrict__ b2,
    const float* __restrict__ g3, const float* __restrict__ b3,
    float* __restrict__ O)
{
    const int row = blockIdx.x, t = threadIdx.x;
    const size_t base = (size_t)row * Dd + t * 4;
    float4 a = *(const float4*)(A + base);
    float4 r = *(const float4*)(R + base);
    float x[4] = {a.x + r.x, a.y + r.y, a.z + r.z, a.w + r.w};

    __shared__ float sh1[4], sh2[4];
    float s = x[0] + x[1] + x[2] + x[3];
    float ss = x[0]*x[0] + x[1]*x[1] + x[2]*x[2] + x[3]*x[3];
#pragma unroll
    for (int o = 16; o; o >>= 1) {
        s  += __shfl_xor_sync(0xffffffffu, s, o);
        ss += __shfl_xor_sync(0xffffffffu, ss, o);
    }
    if (!(t & 31)) { sh1[t >> 5] = s; sh2[t >> 5] = ss; }
    __syncthreads();
    s  = sh1[0] + sh1[1] + sh1[2] + sh1[3];
    ss = sh2[0] + sh2[1] + sh2[2] + sh2[3];
    float mean = s * (1.f / Dd);
    float var = ss * (1.f / Dd) - mean * mean;
    float rs = rsqrtf(var + 1e-5f);

    float4 gg = *(const float4*)(g2 + t * 4);
    float4 bb = *(const float4*)(b2 + t * 4);
    float y[4];
    y[0] = (x[0] - mean) * rs * gg.x + bb.x;
    y[1] = (x[1] - mean) * rs * gg.y + bb.y;
    y[2] = (x[2] - mean) * rs * gg.z + bb.z;
    y[3] = (x[3] - mean) * rs * gg.w + bb.w;

    __syncthreads();
    s  = y[0] + y[1] + y[2] + y[3];
    ss = y[0]*y[0] + y[1]*y[1] + y[2]*y[2] + y[3]*y[3];
#pragma unroll
    for (int o = 16; o; o >>= 1) {
        s  += __shfl_xor_sync(0xffffffffu, s, o);
        ss += __shfl_xor_sync(0xffffffffu, ss, o);
    }
    if (!(t & 31)) { sh1[t >> 5] = s; sh2[t >> 5] = ss; }
    __syncthreads();
    s  = sh1[0] + sh1[1] + sh1[2] + sh1[3];
    ss = sh2[0] + sh2[1] + sh2[2] + sh2[3];
    mean = s * (1.f / Dd);
    var = ss * (1.f / Dd) - mean * mean;
    rs = rsqrtf(var + 1e-5f);

    float4 g3v = *(const float4*)(g3 + t * 4);
    float4 b3v = *(const float4*)(b3 + t * 4);
    float4 o4;
    o4.x = (y[0] - mean) * rs * g3v.x + b3v.x;
    o4.y = (y[1] - mean) * rs * g3v.y + b3v.y;
    o4.z = (y[2] - mean) * rs * g3v.z + b3v.z;
    o4.w = (y[3] - mean) * rs * g3v.w + b3v.w;
    *(float4*)(O + base) = o4;
}

// ---------------- mean pool over S (deterministic 2-stage) ----------------
__global__ void __launch_bounds__(128) colmean_part_k(const float* __restrict__ X,
                                                      float* __restrict__ PP)
{
    const int b = blockIdx.x >> 2;
    const int d = (blockIdx.x & 3) * 128 + threadIdx.x;
    const int sc = blockIdx.y;
    float s = 0.f;
    for (int j = sc * 128; j < sc * 128 + 128; j++)
        s += X[((size_t)(b * Ss + j)) * Dd + d];
    PP[((size_t)sc * Bb + b) * Dd + d] = s;
}

__global__ void __launch_bounds__(128) colmean_fin_k(const float* __restrict__ PP,
                                                     float* __restrict__ P)
{
    const int idx = blockIdx.x * 128 + threadIdx.x;
    const int b = idx / Dd, d = idx % Dd;
    float s = 0.f;
#pragma unroll
    for (int c = 0; c < 16; c++) s += PP[((size_t)c * Bb + b) * Dd + d];
    P[idx] = s * (1.f / Ss);
}

// ---------------- final tiny GEMM ----------------
__global__ void __launch_bounds__(128) final_k(const float* __restrict__ P,
                                               const float* __restrict__ Wt,
                                               const float* __restrict__ bias,
                                               float* __restrict__ out)
{
    const int b = blockIdx.x, o = threadIdx.x;
    float s = bias[o];
    for (int d = 0; d < Dd; d++) s += P[b * Dd + d] * Wt[d * DOUT + o];
    out[b * DOUT + o] = s;
}

// ---------------- launch ----------------
extern "C" void kernel_launch(void* const* d_in, const int* in_sizes, int n_in,
                              void* d_out, int out_size)
{
    const float* x      = (const float*)d_in[0];
    const float* pos    = (const float*)d_in[1];
    const float* win_w  = (const float*)d_in[2];
    const float* win_b  = (const float*)d_in[3];
    const float* l_wqkv = (const float*)d_in[4];
    const float* l_bqkv = (const float*)d_in[5];
    const float* l_wo   = (const float*)d_in[6];
    const float* l_bo   = (const float*)d_in[7];
    const float* g_wqkv = (const float*)d_in[8];
    const float* g_bqkv = (const float*)d_in[9];
    const float* g_wo   = (const float*)d_in[10];
    const float* g_bo   = (const float*)d_in[11];
    const float* gate_w = (const float*)d_in[12];
    const float* gate_b = (const float*)d_in[13];
    const float* ffn_w1 = (const float*)d_in[14];
    const float* ffn_b1 = (const float*)d_in[15];
    const float* ffn_w2 = (const float*)d_in[16];
    const float* ffn_b2 = (const float*)d_in[17];
    const float* n1_g   = (const float*)d_in[18];
    const float* n1_b   = (const float*)d_in[19];
    const float* n2_g   = (const float*)d_in[20];
    const float* n2_b   = (const float*)d_in[21];
    const float* n3_g   = (const float*)d_in[22];
    const float* n3_b   = (const float*)d_in[23];
    const float* out_w  = (const float*)d_in[24];
    const float* out_b  = (const float*)d_in[25];

    float* sp = nullptr;
    cudaGetSymbolAddress((void**)&sp, g_scratch);
    float* bH   = sp + O_H;
    float* bQL  = sp + O_QL;
    float* bKL  = sp + O_KL;
    float* bVL  = sp + O_VL;
    float* bQG  = sp + O_QG;
    float* bKG  = sp + O_KG;
    float* bVG  = sp + O_VG;
    float* bAOL = sp + O_AOL;
    float* bAOG = sp + O_AOG;
    float* bLOC = sp + O_LOC;
    float* bGLO = sp + O_GLO;
    float* bFUS = sp + O_FUS;
    float* bH1  = sp + O_H1;
    float* bFFN = sp + O_FFN;
    float* bH3  = sp + O_H3;
    float* bT1  = sp + O_T1;
    float* bPP  = sp + O_PP;
    float* bP   = sp + O_P;

    static bool attr_set = false;
    if (!attr_set) {
        cudaFuncSetAttribute(flash_tc_k<0>, cudaFuncAttributeMaxDynamicSharedMemorySize,
                             FL_SMEM_BYTES);
        cudaFuncSetAttribute(flash_tc_k<1>, cudaFuncAttributeMaxDynamicSharedMemorySize,
                             FL_SMEM_BYTES);
        attr_set = true;
    }

    const dim3 blk(256);

    // 1. h = x @ win_w + win_b + pos
    gemm_tc_k<1><<<dim3(4, 64), blk>>>(x, nullptr, DIN, 0, win_w, win_b, pos,
                                       nullptr, bH, BS, Dd, DIN);

    // 2. merged 6-slice QKV (local 0..2, global 3..5) -> bQL..bVG
    gemm_tc_k<4><<<dim3(24, 64), blk>>>(bH, g_bqkv, Dd, 0, l_wqkv, l_bqkv,
                                        g_wqkv, nullptr, bQL, BS, Dd, Dd);

    // 3. local banded flash attention
    flash_tc_k<1><<<dim3(Ss / 128, Hh, Bb), 256, FL_SMEM_BYTES>>>(bQL, bKL, bVL, bAOL);

    // 4. global flash attention
    flash_tc_k<0><<<dim3(Ss / 128, Hh, Bb), 256, FL_SMEM_BYTES>>>(bQG, bKG, bVG, bAOG);

    // 5. merged 2-slice output projections -> bLOC, bGLO
    gemm_tc_k<5><<<dim3(8, 64), blk>>>(bAOL, bAOG, Dd, 0, l_wo, l_bo,
                                       g_wo, g_bo, bLOC, BS, Dd, Dd);

    // 6. gate GEMM fused with blend
    gemm_tc_k<3><<<dim3(4, 64), blk>>>(bLOC, bGLO, Dd, Dd, gate_w, gate_b,
                                       bLOC, bGLO, bFUS, BS, Dd, 2 * Dd);

    // 7. h1 = LN(h + fused)
    ln_add_k<<<BS, 128>>>(bH, bFUS, n1_g, n1_b, bH1);

    // 8. FFN
    gemm_tc_k<2><<<dim3(8, 64), blk>>>(bH1, nullptr, Dd, 0, ffn_w1, ffn_b1,
                                       nullptr, nullptr, bT1, BS, 2 * Dd, Dd);
    gemm_tc_k<0><<<dim3(4, 64), blk>>>(bT1, nullptr, 2 * Dd, 0, ffn_w2, ffn_b2,
                                       nullptr, nullptr, bFFN, BS, Dd, 2 * Dd);

    // 9. h3 = LN(LN(h1 + ffn))
    ln_add_ln_k<<<BS, 128>>>(bH1, bFFN, n2_g, n2_b, n3_g, n3_b, bH3);

    // 10. mean-pool over S, then final projection
    colmean_part_k<<<dim3(Bb * 4, 16), 128>>>(bH3, bPP);
    colmean_fin_k<<<(Bb * Dd) / 128, 128>>>(bPP, bP);
    final_k<<<Bb, DOUT>>>(bP, out_w, out_b, (float*)d_out);

    (void)in_sizes; (void)n_in; (void)out_size;
}